// round 9
// baseline (speedup 1.0000x reference)
#include <cuda_runtime.h>
#include <math.h>

// ---------------- scratch (device globals, no allocation) ----------------
__device__ float g_feats[8192 * 8];
__device__ float g_C[256 * 256];   // rows 0-127: Re(U[128:256,:]), rows 128-255: Im
__device__ float g_M[256 * 256];
__device__ float g_T[6561];
__device__ float2 g_G[17][16];

// ---------------- complex helpers ----------------
__device__ __forceinline__ float2 cmul(float2 a, float2 b) {
    return make_float2(a.x * b.x - a.y * b.y, a.x * b.y + a.y * b.x);
}
__device__ __forceinline__ float2 cadd(float2 a, float2 b) {
    return make_float2(a.x + b.x, a.y + b.y);
}

__constant__ float2 c_P[4][2][2] = {
    { { {1.f,0.f},{0.f,0.f} }, { {0.f,0.f},{1.f,0.f} } },   // I
    { { {0.f,0.f},{1.f,0.f} }, { {1.f,0.f},{0.f,0.f} } },   // X
    { { {0.f,0.f},{0.f,-1.f} }, { {0.f,1.f},{0.f,0.f} } },  // Y
    { { {1.f,0.f},{0.f,0.f} }, { {0.f,0.f},{-1.f,0.f} } },  // Z
};

__constant__ int c_gwa[17] = {0,2,4,6,1,3,5, 1,3,5,7, 0,4,2, 2,6, 0};
__constant__ int c_gwb[17] = {1,3,5,7,2,4,6, 0,2,4,6, 2,6,4, 0,4, 4};

// ---------------- K1: feats = tanh(x @ fc_w^T + fc_b) ----------------
// 256 blocks x 512 threads, 2 rows/warp (32 rows/block), 96KB smem,
// 2 blocks/SM -> 32 warps/SM.
__global__ __launch_bounds__(512, 2) void feats_kernel(const float* __restrict__ x,
                                                       const float* __restrict__ fcw,
                                                       const float* __restrict__ fcb) {
    extern __shared__ float wsh[];  // 8*3072 floats = 96KB
    int tid = threadIdx.x;
    for (int i = tid * 4; i < 8 * 3072; i += 512 * 4)
        *(float4*)&wsh[i] = *(const float4*)&fcw[i];
    __syncthreads();

    int warp = tid >> 5, lane = tid & 31;
    long long row0 = ((long long)blockIdx.x * 16 + warp) * 2;  // 0..8190

    float acc[8][2];
#pragma unroll
    for (int q = 0; q < 8; q++) { acc[q][0] = 0.f; acc[q][1] = 0.f; }

#pragma unroll 4
    for (int it = 0; it < 24; it++) {
        int c = (it * 32 + lane) * 4;
        float4 xv0 = *(const float4*)&x[row0 * 3072 + c];
        float4 xv1 = *(const float4*)&x[(row0 + 1) * 3072 + c];
#pragma unroll
        for (int q = 0; q < 8; q++) {
            float4 wv = *(const float4*)&wsh[q * 3072 + c];
            acc[q][0] += wv.x * xv0.x + wv.y * xv0.y + wv.z * xv0.z + wv.w * xv0.w;
            acc[q][1] += wv.x * xv1.x + wv.y * xv1.y + wv.z * xv1.z + wv.w * xv1.w;
        }
    }
#pragma unroll
    for (int q = 0; q < 8; q++) {
#pragma unroll
        for (int r = 0; r < 2; r++) {
            float v = acc[q][r];
            v += __shfl_down_sync(0xffffffffu, v, 16);
            v += __shfl_down_sync(0xffffffffu, v, 8);
            v += __shfl_down_sync(0xffffffffu, v, 4);
            v += __shfl_down_sync(0xffffffffu, v, 2);
            v += __shfl_down_sync(0xffffffffu, v, 1);
            if (lane == 0) g_feats[(row0 + r) * 8 + q] = tanhf(v + fcb[q]);
        }
    }
}

// ---------------- gate construction ----------------
__device__ __forceinline__ void u3g(float th, float ph, float dl, float2 g[2][2]) {
    float st, ct; __sincosf(0.5f * th, &st, &ct);
    float sp, cp; __sincosf(ph, &sp, &cp);
    float sd, cd; __sincosf(dl, &sd, &cd);
    float spd, cpd; __sincosf(ph + dl, &spd, &cpd);
    g[0][0] = make_float2(ct, 0.f);
    g[0][1] = make_float2(-cd * st, -sd * st);
    g[1][0] = make_float2(cp * st, sp * st);
    g[1][1] = make_float2(cpd * ct, spd * ct);
}

__device__ __forceinline__ void zero4(float2 g[4][4]) {
#pragma unroll
    for (int r = 0; r < 4; r++)
#pragma unroll
        for (int c = 0; c < 4; c++) g[r][c] = make_float2(0.f, 0.f);
}

__device__ __forceinline__ void kron22(const float2 A[2][2], const float2 B[2][2],
                                       float2 P[4][4]) {
#pragma unroll
    for (int ra = 0; ra < 2; ra++)
#pragma unroll
        for (int rb = 0; rb < 2; rb++)
#pragma unroll
            for (int ca = 0; ca < 2; ca++)
#pragma unroll
                for (int cb = 0; cb < 2; cb++)
                    P[ra * 2 + rb][ca * 2 + cb] = cmul(A[ra][ca], B[rb][cb]);
}

__device__ __forceinline__ void mm4(const float2 A[4][4], const float2 B[4][4],
                                    float2 C[4][4]) {
#pragma unroll
    for (int i = 0; i < 4; i++)
#pragma unroll
        for (int j = 0; j < 4; j++) {
            float2 s = make_float2(0.f, 0.f);
#pragma unroll
            for (int k = 0; k < 4; k++) s = cadd(s, cmul(A[i][k], B[k][j]));
            C[i][j] = s;
        }
}

// one warp: threads 0..15 build gates 0..15; then whole warp tree-builds g16.
__global__ __launch_bounds__(32) void gates_kernel(const float* __restrict__ conv,
                                                   const float* __restrict__ pool,
                                                   const float* __restrict__ last) {
    __shared__ float2 Psh[16][16];   // tree workspace (16 4x4 matrices)
    int g = threadIdx.x;

    // ---- gates 0..15 (one per thread) ----
    if (g < 16) {
        float2 G[4][4];
        bool is_conv = (g <= 6) || (g >= 11 && g <= 13);
        if (is_conv) {
            int layer, idx;
            if (g <= 6) { const int ii[7] = {0, 2, 4, 6, 1, 3, 5}; layer = 0; idx = ii[g]; }
            else        { const int ii[3] = {0, 2, 1};             layer = 1; idx = ii[g - 11]; }
            const float* cw = conv + layer * 8 * 15;
            float2 A1[2][2], B1[2][2], A2[2][2], B2[2][2];
            u3g(cw[idx * 15 + 0], cw[idx * 15 + 1], cw[idx * 15 + 2], A1);
            u3g(cw[(idx + 1) * 15 + 3], cw[(idx + 1) * 15 + 4], cw[(idx + 1) * 15 + 5], B1);
            u3g(cw[idx * 15 + 9], cw[idx * 15 + 10], cw[idx * 15 + 11], A2);
            u3g(cw[(idx + 1) * 15 + 12], cw[(idx + 1) * 15 + 13], cw[(idx + 1) * 15 + 14], B2);
            float2 P1[4][4], P2[4][4], T1[4][4], T2[4][4], IS[4][4];
            kron22(A1, B1, P1);
            kron22(A2, B2, P2);
            { // ZZ
                float sn, cs; __sincosf(0.5f * cw[idx * 15 + 6], &sn, &cs);
                zero4(IS);
                IS[0][0] = make_float2(cs, -sn);
                IS[1][1] = make_float2(cs, sn);
                IS[2][2] = make_float2(cs, sn);
                IS[3][3] = make_float2(cs, -sn);
                mm4(IS, P1, T1);
            }
            { // YY
                float sn, cs; __sincosf(0.5f * cw[idx * 15 + 7], &sn, &cs);
                zero4(IS);
                IS[0][0] = IS[1][1] = IS[2][2] = IS[3][3] = make_float2(cs, 0.f);
                IS[0][3] = make_float2(0.f, sn);
                IS[1][2] = make_float2(0.f, -sn);
                IS[2][1] = make_float2(0.f, -sn);
                IS[3][0] = make_float2(0.f, sn);
                mm4(IS, T1, T2);
            }
            { // XX
                float sn, cs; __sincosf(0.5f * cw[idx * 15 + 8], &sn, &cs);
                zero4(IS);
                IS[0][0] = IS[1][1] = IS[2][2] = IS[3][3] = make_float2(cs, 0.f);
                IS[0][3] = IS[1][2] = IS[2][1] = IS[3][0] = make_float2(0.f, -sn);
                mm4(IS, T2, T1);
            }
            mm4(P2, T1, G);
        } else {
            int layer = (g <= 10) ? 0 : 1;
            int pi = (g <= 10) ? (g - 7) : (g - 14);
            const float* pw = pool + layer * 4 * 3;
            float2 u[2][2];
            u3g(pw[pi * 3 + 0], pw[pi * 3 + 1], pw[pi * 3 + 2], u);
            zero4(G);
            G[0][0] = make_float2(1.f, 0.f);
            G[1][1] = make_float2(1.f, 0.f);
            G[2][2] = u[0][0]; G[2][3] = u[0][1];
            G[3][2] = u[1][0]; G[3][3] = u[1][1];
        }
#pragma unroll
        for (int r = 0; r < 4; r++)
#pragma unroll
            for (int c = 0; c < 4; c++) g_G[g][r * 4 + c] = G[r][c];
    }

    // ---- gate 16: product of 15 Pauli rotations, built by tree ----
    // lanes 0..14 build M_kk; lane 15 contributes identity. Final product is
    // M14*M13*...*M0 (kk applied in order 0..14, each left-multiplied).
    {
        float2 Mk[4][4];
        if (g < 15) {
            int pa = (g + 1) >> 2, pb = (g + 1) & 3;
            float sn, cs; __sincosf(0.5f * last[g], &sn, &cs);
#pragma unroll
            for (int r = 0; r < 4; r++)
#pragma unroll
                for (int c = 0; c < 4; c++) {
                    float2 p2 = cmul(c_P[pa][r >> 1][c >> 1], c_P[pb][r & 1][c & 1]);
                    Mk[r][c] = make_float2((r == c ? cs : 0.f) + sn * p2.y, -sn * p2.x);
                }
        } else {
            zero4(Mk);
#pragma unroll
            for (int i = 0; i < 4; i++) Mk[i][i] = make_float2(1.f, 0.f);
        }
        if (g < 16) {
#pragma unroll
            for (int r = 0; r < 4; r++)
#pragma unroll
                for (int c = 0; c < 4; c++) Psh[g][r * 4 + c] = Mk[r][c];
        }
        __syncwarp();
        // tree: level n combines P[2i+1]*P[2i] -> P[i]
        for (int cnt = 8; cnt >= 1; cnt >>= 1) {
            if (g < cnt) {
                float2 A[4][4], B[4][4], R[4][4];
#pragma unroll
                for (int r = 0; r < 4; r++)
#pragma unroll
                    for (int c = 0; c < 4; c++) {
                        A[r][c] = Psh[2 * g + 1][r * 4 + c];
                        B[r][c] = Psh[2 * g][r * 4 + c];
                    }
                mm4(A, B, R);
                __syncwarp(0xffffffffu >> (32 - cnt));
#pragma unroll
                for (int r = 0; r < 4; r++)
#pragma unroll
                    for (int c = 0; c < 4; c++) Psh[g][r * 4 + c] = R[r][c];
            }
            __syncwarp();
        }
        if (g == 0) {
#pragma unroll
            for (int r = 0; r < 4; r++)
#pragma unroll
                for (int c = 0; c < 4; c++) g_G[16][r * 4 + c] = Psh[0][r * 4 + c];
        }
    }
}

// ---------------- K2: apply 17 fused gates; store bottom-half of U ----------------
__device__ __forceinline__ void apply2(float2* s, const float2 g[4][4], int wa, int wb, int t) {
    __syncthreads();
    int ma = 1 << (7 - wa), mb = 1 << (7 - wb);
    int lo = ma < mb ? ma : mb;
    int hi = ma < mb ? mb : ma;
    int k = t;
    k = ((k & ~(lo - 1)) << 1) | (k & (lo - 1));
    k = ((k & ~(hi - 1)) << 1) | (k & (hi - 1));
    int i0 = k, i1 = k | mb, i2 = k | ma, i3 = k | ma | mb;
    float2 v0 = s[i0], v1 = s[i1], v2 = s[i2], v3 = s[i3];
    float2 o0 = cadd(cadd(cmul(g[0][0], v0), cmul(g[0][1], v1)),
                     cadd(cmul(g[0][2], v2), cmul(g[0][3], v3)));
    float2 o1 = cadd(cadd(cmul(g[1][0], v0), cmul(g[1][1], v1)),
                     cadd(cmul(g[1][2], v2), cmul(g[1][3], v3)));
    float2 o2 = cadd(cadd(cmul(g[2][0], v0), cmul(g[2][1], v1)),
                     cadd(cmul(g[2][2], v2), cmul(g[2][3], v3)));
    float2 o3 = cadd(cadd(cmul(g[3][0], v0), cmul(g[3][1], v1)),
                     cadd(cmul(g[3][2], v2), cmul(g[3][3], v3)));
    s[i0] = o0; s[i1] = o1; s[i2] = o2; s[i3] = o3;
}

__global__ __launch_bounds__(64) void circuit_kernel() {
    __shared__ float2 s[256];
    int t = threadIdx.x;
    int col = blockIdx.x;
    for (int k = t; k < 256; k += 64)
        s[k] = make_float2(k == col ? 1.f : 0.f, 0.f);

    for (int g = 0; g < 17; g++) {
        float2 g4[4][4];
        const float2* Gp = &g_G[g][0];
#pragma unroll
        for (int r = 0; r < 4; r++)
#pragma unroll
            for (int c = 0; c < 4; c++) g4[r][c] = Gp[r * 4 + c];
        apply2(s, g4, c_gwa[g], c_gwb[g], t);
    }
    __syncthreads();
    for (int k = t; k < 128; k += 64) {
        g_C[k * 256 + col]         = s[k + 128].x;
        g_C[(k + 128) * 256 + col] = s[k + 128].y;
    }
}

// ---------------- K3: M = I - 2 C^T C (64 blocks, 32x32 tiles, 2x2/thread) --------
__global__ __launch_bounds__(256) void msyrk_kernel() {
    int bi = (blockIdx.x >> 3) * 32, bj = (blockIdx.x & 7) * 32;
    __shared__ float As[32][33], Bs[32][33];
    int tx = threadIdx.x & 15, ty = threadIdx.x >> 4;
    float a00 = 0.f, a01 = 0.f, a10 = 0.f, a11 = 0.f;

    for (int k0 = 0; k0 < 256; k0 += 32) {
        for (int idx = threadIdx.x; idx < 1024; idx += 256) {
            int r = idx >> 5, c = idx & 31;
            As[r][c] = g_C[(k0 + r) * 256 + bi + c];
            Bs[r][c] = g_C[(k0 + r) * 256 + bj + c];
        }
        __syncthreads();
#pragma unroll
        for (int kk = 0; kk < 32; kk++) {
            float a0 = As[kk][ty * 2], a1 = As[kk][ty * 2 + 1];
            float b0 = Bs[kk][tx * 2], b1 = Bs[kk][tx * 2 + 1];
            a00 = fmaf(a0, b0, a00); a01 = fmaf(a0, b1, a01);
            a10 = fmaf(a1, b0, a10); a11 = fmaf(a1, b1, a11);
        }
        __syncthreads();
    }
    int gi = bi + ty * 2, gj = bj + tx * 2;
    g_M[gi * 256 + gj]           = (gi == gj ? 1.f : 0.f) - 2.f * a00;
    g_M[gi * 256 + gj + 1]       = (gi == gj + 1 ? 1.f : 0.f) - 2.f * a01;
    g_M[(gi + 1) * 256 + gj]     = (gi + 1 == gj ? 1.f : 0.f) - 2.f * a10;
    g_M[(gi + 1) * 256 + gj + 1] = (gi == gj ? 1.f : 0.f) - 2.f * a11;
}

// ---------------- K4: M -> T. 9 blocks: digits (p0,p1) fused from gmem ----------
__device__ __forceinline__ void pdec(int p, int* r, int* c, float* sg) {
    if (p == 2) { r[0] = 0; c[0] = 1; r[1] = 1; c[1] = 0; sg[0] = 1.f; sg[1] = 1.f; }
    else        { r[0] = 0; c[0] = 0; r[1] = 1; c[1] = 1; sg[0] = 1.f; sg[1] = (p == 0 ? 1.f : -1.f); }
}

__global__ __launch_bounds__(256) void pauli_kernel() {
    __shared__ float S[4096];
    int t = threadIdx.x;
    int p0 = blockIdx.x / 3, p1 = blockIdx.x % 3;
    int r0[2], c0[2], r1[2], c1[2];
    float s0[2], s1[2];
    pdec(p0, r0, c0, s0);
    pdec(p1, r1, c1, s1);

    for (int o = t; o < 4096; o += 256) {
        int i = o >> 6, j = o & 63;
        float v = 0.f;
#pragma unroll
        for (int t0 = 0; t0 < 2; t0++)
#pragma unroll
            for (int t1 = 0; t1 < 2; t1++)
                v += s0[t0] * s1[t1] *
                     g_M[(i + 128 * r0[t0] + 64 * r1[t1]) * 256 +
                         (j + 128 * c0[t0] + 64 * c1[t1])];
        S[o] = v;
    }
    __syncthreads();

    int nc = 1;
    for (int d = 2; d < 8; d++) {
        int sh = 7 - d;
        int half = 1 << sh;
        int hh = half * half;
        int n_out = nc * 3 * hh;
        int in_blk = 4 * hh;
        int full = half << 1;
        float reg[12];
#pragma unroll
        for (int u = 0; u < 12; u++) {
            int o = t + (u << 8);
            if (o < n_out) {
                int j = o & (half - 1);
                int rr = o >> sh;
                int i = rr & (half - 1);
                int r2 = rr >> sh;
                int p = r2 % 3;
                int c = r2 / 3;
                const float* base = S + c * in_blk;
                float v;
                if (p == 0)      v = base[i * full + j] + base[(i + half) * full + j + half];
                else if (p == 1) v = base[i * full + j] - base[(i + half) * full + j + half];
                else             v = base[i * full + j + half] + base[(i + half) * full + j];
                reg[u] = v;
            }
        }
        __syncthreads();
#pragma unroll
        for (int u = 0; u < 12; u++) {
            int o = t + (u << 8);
            if (o < n_out) S[o] = reg[u];
        }
        __syncthreads();
        nc *= 3;
    }
    for (int o = t; o < 729; o += 256)
        g_T[blockIdx.x * 729 + o] = S[o];
}

// ---------------- K5: qval = a^T T b / 256; logits ----------------
__device__ __forceinline__ float selt(int d, float c, float s) {
    return d == 0 ? 1.f : (d == 1 ? c : s);
}

__global__ __launch_bounds__(256) void logits_kernel(const float* __restrict__ out_w,
                                                     const float* __restrict__ out_b,
                                                     float* __restrict__ out) {
    extern __shared__ float sm[];
    float* Tsh = sm;                 // 81*84
    float* ash = Tsh + 81 * 84;      // 64*84
    float* bsh = ash + 64 * 84;      // 64*84
    float* qps = bsh + 64 * 84;      // 64*16
    float* qvs = qps + 64 * 16;      // 64

    int t = threadIdx.x;
    for (int i = t; i < 81 * 84; i += 256) Tsh[i] = 0.f;
    for (int i = t; i < 64 * 84; i += 256) bsh[i] = 0.f;
    __syncthreads();
    for (int i = t; i < 6561; i += 256) Tsh[(i / 81) * 84 + (i % 81)] = g_T[i];

    {
        int s = t >> 2, part = t & 3;
        int sg = blockIdx.x * 64 + s;
        float tc[8], ts[8];
#pragma unroll
        for (int w = 0; w < 8; w++) {
            float f = g_feats[sg * 8 + w];
            __sincosf(f, &ts[w], &tc[w]);
        }
        int m0 = part * 21;
        int m1 = m0 + 21; if (m1 > 81) m1 = 81;
        for (int m = m0; m < m1; m++) {
            int d0 = m / 27, d1 = (m / 9) % 3, d2 = (m / 3) % 3, d3 = m % 3;
            ash[s * 84 + m] = selt(d0, tc[0], ts[0]) * selt(d1, tc[1], ts[1]) *
                              selt(d2, tc[2], ts[2]) * selt(d3, tc[3], ts[3]);
            bsh[s * 84 + m] = selt(d0, tc[4], ts[4]) * selt(d1, tc[5], ts[5]) *
                              selt(d2, tc[6], ts[6]) * selt(d3, tc[7], ts[7]);
        }
    }
    __syncthreads();

    if (t < 224) {
        int sg = t / 14, ng = t % 14;
        int s0 = sg * 4, n0 = ng * 6;
        float e[4][6];
#pragma unroll
        for (int i = 0; i < 4; i++)
#pragma unroll
            for (int j = 0; j < 6; j++) e[i][j] = 0.f;
        for (int m = 0; m < 81; m++) {
            float tv[6];
#pragma unroll
            for (int j = 0; j < 6; j++) tv[j] = Tsh[m * 84 + n0 + j];
#pragma unroll
            for (int i = 0; i < 4; i++) {
                float av = ash[(s0 + i) * 84 + m];
#pragma unroll
                for (int j = 0; j < 6; j++) e[i][j] = fmaf(av, tv[j], e[i][j]);
            }
        }
#pragma unroll
        for (int i = 0; i < 4; i++) {
            float q = 0.f;
#pragma unroll
            for (int j = 0; j < 6; j++) q += e[i][j] * bsh[(s0 + i) * 84 + n0 + j];
            qps[(s0 + i) * 16 + ng] = q;
        }
    }
    __syncthreads();
    if (t < 64) {
        float q = 0.f;
#pragma unroll
        for (int k = 0; k < 14; k++) q += qps[t * 16 + k];
        qvs[t] = q * (1.0f / 256.0f);
    }
    __syncthreads();
    for (int i = t; i < 640; i += 256) {
        int s = i / 10, c = i % 10;
        out[(blockIdx.x * 64 + s) * 10 + c] = qvs[s] * out_w[c] + out_b[c];
    }
}

// ---------------- launch: single stream, no contention ----------------
extern "C" void kernel_launch(void* const* d_in, const int* in_sizes, int n_in,
                              void* d_out, int out_size) {
    const float* x     = (const float*)d_in[0];
    const float* fcw   = (const float*)d_in[1];
    const float* fcb   = (const float*)d_in[2];
    const float* conv  = (const float*)d_in[3];
    const float* pool  = (const float*)d_in[4];
    const float* last  = (const float*)d_in[5];
    const float* out_w = (const float*)d_in[6];
    const float* out_b = (const float*)d_in[7];
    float* out = (float*)d_out;

    static bool inited = false;
    if (!inited) {
        cudaFuncSetAttribute(feats_kernel, cudaFuncAttributeMaxDynamicSharedMemorySize, 8 * 3072 * 4);
        cudaFuncSetAttribute(logits_kernel, cudaFuncAttributeMaxDynamicSharedMemorySize, 18644 * 4);
        inited = true;
    }

    gates_kernel<<<1, 32>>>(conv, pool, last);
    circuit_kernel<<<256, 64>>>();
    msyrk_kernel<<<64, 256>>>();
    pauli_kernel<<<9, 256>>>();
    feats_kernel<<<256, 512, 8 * 3072 * 4>>>(x, fcw, fcb);
    logits_kernel<<<128, 256, 18644 * 4>>>(out_w, out_b, out);
}

// round 10
// speedup vs baseline: 1.0076x; 1.0076x over previous
#include <cuda_runtime.h>
#include <math.h>

// ---------------- scratch (device globals, no allocation) ----------------
__device__ float g_feats[8192 * 8];
__device__ float g_C[256 * 256];   // rows 0-127: Re(U[128:256,:]), rows 128-255: Im
__device__ float g_M[256 * 256];
__device__ float g_T[6561];
__device__ float2 g_G[17][16];

// ---------------- complex helpers ----------------
__device__ __forceinline__ float2 cmul(float2 a, float2 b) {
    return make_float2(a.x * b.x - a.y * b.y, a.x * b.y + a.y * b.x);
}
__device__ __forceinline__ float2 cadd(float2 a, float2 b) {
    return make_float2(a.x + b.x, a.y + b.y);
}

__constant__ float2 c_P[4][2][2] = {
    { { {1.f,0.f},{0.f,0.f} }, { {0.f,0.f},{1.f,0.f} } },   // I
    { { {0.f,0.f},{1.f,0.f} }, { {1.f,0.f},{0.f,0.f} } },   // X
    { { {0.f,0.f},{0.f,-1.f} }, { {0.f,1.f},{0.f,0.f} } },  // Y
    { { {1.f,0.f},{0.f,0.f} }, { {0.f,0.f},{-1.f,0.f} } },  // Z
};

__constant__ int c_gwa[17] = {0,2,4,6,1,3,5, 1,3,5,7, 0,4,2, 2,6, 0};
__constant__ int c_gwb[17] = {1,3,5,7,2,4,6, 0,2,4,6, 2,6,4, 0,4, 4};

// ---------------- K1: feats = tanh(x @ fc_w^T + fc_b) ----------------
// 256 blocks x 512 threads, 2 rows/warp (32 rows/block), 96KB smem,
// 2 blocks/SM -> 32 warps/SM. Runs FIRST: ramps clocks with HBM-bound work.
__global__ __launch_bounds__(512, 2) void feats_kernel(const float* __restrict__ x,
                                                       const float* __restrict__ fcw,
                                                       const float* __restrict__ fcb) {
    extern __shared__ float wsh[];  // 8*3072 floats = 96KB
    int tid = threadIdx.x;
    for (int i = tid * 4; i < 8 * 3072; i += 512 * 4)
        *(float4*)&wsh[i] = *(const float4*)&fcw[i];
    __syncthreads();

    int warp = tid >> 5, lane = tid & 31;
    long long row0 = ((long long)blockIdx.x * 16 + warp) * 2;  // 0..8190

    float acc[8][2];
#pragma unroll
    for (int q = 0; q < 8; q++) { acc[q][0] = 0.f; acc[q][1] = 0.f; }

#pragma unroll 4
    for (int it = 0; it < 24; it++) {
        int c = (it * 32 + lane) * 4;
        float4 xv0 = *(const float4*)&x[row0 * 3072 + c];
        float4 xv1 = *(const float4*)&x[(row0 + 1) * 3072 + c];
#pragma unroll
        for (int q = 0; q < 8; q++) {
            float4 wv = *(const float4*)&wsh[q * 3072 + c];
            acc[q][0] += wv.x * xv0.x + wv.y * xv0.y + wv.z * xv0.z + wv.w * xv0.w;
            acc[q][1] += wv.x * xv1.x + wv.y * xv1.y + wv.z * xv1.z + wv.w * xv1.w;
        }
    }
#pragma unroll
    for (int q = 0; q < 8; q++) {
#pragma unroll
        for (int r = 0; r < 2; r++) {
            float v = acc[q][r];
            v += __shfl_down_sync(0xffffffffu, v, 16);
            v += __shfl_down_sync(0xffffffffu, v, 8);
            v += __shfl_down_sync(0xffffffffu, v, 4);
            v += __shfl_down_sync(0xffffffffu, v, 2);
            v += __shfl_down_sync(0xffffffffu, v, 1);
            if (lane == 0) g_feats[(row0 + r) * 8 + q] = tanhf(v + fcb[q]);
        }
    }
}

// ---------------- gate construction ----------------
__device__ __forceinline__ void u3g(float th, float ph, float dl, float2 g[2][2]) {
    float st, ct; __sincosf(0.5f * th, &st, &ct);
    float sp, cp; __sincosf(ph, &sp, &cp);
    float sd, cd; __sincosf(dl, &sd, &cd);
    float spd, cpd; __sincosf(ph + dl, &spd, &cpd);
    g[0][0] = make_float2(ct, 0.f);
    g[0][1] = make_float2(-cd * st, -sd * st);
    g[1][0] = make_float2(cp * st, sp * st);
    g[1][1] = make_float2(cpd * ct, spd * ct);
}

__device__ __forceinline__ void zero4(float2 g[4][4]) {
#pragma unroll
    for (int r = 0; r < 4; r++)
#pragma unroll
        for (int c = 0; c < 4; c++) g[r][c] = make_float2(0.f, 0.f);
}

__device__ __forceinline__ void kron22(const float2 A[2][2], const float2 B[2][2],
                                       float2 P[4][4]) {
#pragma unroll
    for (int ra = 0; ra < 2; ra++)
#pragma unroll
        for (int rb = 0; rb < 2; rb++)
#pragma unroll
            for (int ca = 0; ca < 2; ca++)
#pragma unroll
                for (int cb = 0; cb < 2; cb++)
                    P[ra * 2 + rb][ca * 2 + cb] = cmul(A[ra][ca], B[rb][cb]);
}

__device__ __forceinline__ void mm4(const float2 A[4][4], const float2 B[4][4],
                                    float2 C[4][4]) {
#pragma unroll
    for (int i = 0; i < 4; i++)
#pragma unroll
        for (int j = 0; j < 4; j++) {
            float2 s = make_float2(0.f, 0.f);
#pragma unroll
            for (int k = 0; k < 4; k++) s = cadd(s, cmul(A[i][k], B[k][j]));
            C[i][j] = s;
        }
}

// one warp: threads 0..15 build gates 0..15; then whole warp tree-builds g16.
__global__ __launch_bounds__(32) void gates_kernel(const float* __restrict__ conv,
                                                   const float* __restrict__ pool,
                                                   const float* __restrict__ last) {
    __shared__ float2 Psh[16][16];   // tree workspace (16 4x4 matrices)
    int g = threadIdx.x;

    // ---- gates 0..15 (one per thread) ----
    if (g < 16) {
        float2 G[4][4];
        bool is_conv = (g <= 6) || (g >= 11 && g <= 13);
        if (is_conv) {
            int layer, idx;
            if (g <= 6) { const int ii[7] = {0, 2, 4, 6, 1, 3, 5}; layer = 0; idx = ii[g]; }
            else        { const int ii[3] = {0, 2, 1};             layer = 1; idx = ii[g - 11]; }
            const float* cw = conv + layer * 8 * 15;
            float2 A1[2][2], B1[2][2], A2[2][2], B2[2][2];
            u3g(cw[idx * 15 + 0], cw[idx * 15 + 1], cw[idx * 15 + 2], A1);
            u3g(cw[(idx + 1) * 15 + 3], cw[(idx + 1) * 15 + 4], cw[(idx + 1) * 15 + 5], B1);
            u3g(cw[idx * 15 + 9], cw[idx * 15 + 10], cw[idx * 15 + 11], A2);
            u3g(cw[(idx + 1) * 15 + 12], cw[(idx + 1) * 15 + 13], cw[(idx + 1) * 15 + 14], B2);
            float2 P1[4][4], P2[4][4], T1[4][4], T2[4][4], IS[4][4];
            kron22(A1, B1, P1);
            kron22(A2, B2, P2);
            { // ZZ
                float sn, cs; __sincosf(0.5f * cw[idx * 15 + 6], &sn, &cs);
                zero4(IS);
                IS[0][0] = make_float2(cs, -sn);
                IS[1][1] = make_float2(cs, sn);
                IS[2][2] = make_float2(cs, sn);
                IS[3][3] = make_float2(cs, -sn);
                mm4(IS, P1, T1);
            }
            { // YY
                float sn, cs; __sincosf(0.5f * cw[idx * 15 + 7], &sn, &cs);
                zero4(IS);
                IS[0][0] = IS[1][1] = IS[2][2] = IS[3][3] = make_float2(cs, 0.f);
                IS[0][3] = make_float2(0.f, sn);
                IS[1][2] = make_float2(0.f, -sn);
                IS[2][1] = make_float2(0.f, -sn);
                IS[3][0] = make_float2(0.f, sn);
                mm4(IS, T1, T2);
            }
            { // XX
                float sn, cs; __sincosf(0.5f * cw[idx * 15 + 8], &sn, &cs);
                zero4(IS);
                IS[0][0] = IS[1][1] = IS[2][2] = IS[3][3] = make_float2(cs, 0.f);
                IS[0][3] = IS[1][2] = IS[2][1] = IS[3][0] = make_float2(0.f, -sn);
                mm4(IS, T2, T1);
            }
            mm4(P2, T1, G);
        } else {
            int layer = (g <= 10) ? 0 : 1;
            int pi = (g <= 10) ? (g - 7) : (g - 14);
            const float* pw = pool + layer * 4 * 3;
            float2 u[2][2];
            u3g(pw[pi * 3 + 0], pw[pi * 3 + 1], pw[pi * 3 + 2], u);
            zero4(G);
            G[0][0] = make_float2(1.f, 0.f);
            G[1][1] = make_float2(1.f, 0.f);
            G[2][2] = u[0][0]; G[2][3] = u[0][1];
            G[3][2] = u[1][0]; G[3][3] = u[1][1];
        }
#pragma unroll
        for (int r = 0; r < 4; r++)
#pragma unroll
            for (int c = 0; c < 4; c++) g_G[g][r * 4 + c] = G[r][c];
    }

    // ---- gate 16: product of 15 Pauli rotations, built by tree ----
    {
        float2 Mk[4][4];
        if (g < 15) {
            int pa = (g + 1) >> 2, pb = (g + 1) & 3;
            float sn, cs; __sincosf(0.5f * last[g], &sn, &cs);
#pragma unroll
            for (int r = 0; r < 4; r++)
#pragma unroll
                for (int c = 0; c < 4; c++) {
                    float2 p2 = cmul(c_P[pa][r >> 1][c >> 1], c_P[pb][r & 1][c & 1]);
                    Mk[r][c] = make_float2((r == c ? cs : 0.f) + sn * p2.y, -sn * p2.x);
                }
        } else {
            zero4(Mk);
#pragma unroll
            for (int i = 0; i < 4; i++) Mk[i][i] = make_float2(1.f, 0.f);
        }
        if (g < 16) {
#pragma unroll
            for (int r = 0; r < 4; r++)
#pragma unroll
                for (int c = 0; c < 4; c++) Psh[g][r * 4 + c] = Mk[r][c];
        }
        __syncwarp();
        for (int cnt = 8; cnt >= 1; cnt >>= 1) {
            if (g < cnt) {
                float2 A[4][4], B[4][4], R[4][4];
#pragma unroll
                for (int r = 0; r < 4; r++)
#pragma unroll
                    for (int c = 0; c < 4; c++) {
                        A[r][c] = Psh[2 * g + 1][r * 4 + c];
                        B[r][c] = Psh[2 * g][r * 4 + c];
                    }
                mm4(A, B, R);
                __syncwarp(0xffffffffu >> (32 - cnt));
#pragma unroll
                for (int r = 0; r < 4; r++)
#pragma unroll
                    for (int c = 0; c < 4; c++) Psh[g][r * 4 + c] = R[r][c];
            }
            __syncwarp();
        }
        if (g == 0) {
#pragma unroll
            for (int r = 0; r < 4; r++)
#pragma unroll
                for (int c = 0; c < 4; c++) g_G[16][r * 4 + c] = Psh[0][r * 4 + c];
        }
    }
}

// ---------------- K2: apply 17 fused gates; store bottom-half of U ----------------
__device__ __forceinline__ void apply2(float2* s, const float2 g[4][4], int wa, int wb, int t) {
    __syncthreads();
    int ma = 1 << (7 - wa), mb = 1 << (7 - wb);
    int lo = ma < mb ? ma : mb;
    int hi = ma < mb ? mb : ma;
    int k = t;
    k = ((k & ~(lo - 1)) << 1) | (k & (lo - 1));
    k = ((k & ~(hi - 1)) << 1) | (k & (hi - 1));
    int i0 = k, i1 = k | mb, i2 = k | ma, i3 = k | ma | mb;
    float2 v0 = s[i0], v1 = s[i1], v2 = s[i2], v3 = s[i3];
    float2 o0 = cadd(cadd(cmul(g[0][0], v0), cmul(g[0][1], v1)),
                     cadd(cmul(g[0][2], v2), cmul(g[0][3], v3)));
    float2 o1 = cadd(cadd(cmul(g[1][0], v0), cmul(g[1][1], v1)),
                     cadd(cmul(g[1][2], v2), cmul(g[1][3], v3)));
    float2 o2 = cadd(cadd(cmul(g[2][0], v0), cmul(g[2][1], v1)),
                     cadd(cmul(g[2][2], v2), cmul(g[2][3], v3)));
    float2 o3 = cadd(cadd(cmul(g[3][0], v0), cmul(g[3][1], v1)),
                     cadd(cmul(g[3][2], v2), cmul(g[3][3], v3)));
    s[i0] = o0; s[i1] = o1; s[i2] = o2; s[i3] = o3;
}

__global__ __launch_bounds__(64) void circuit_kernel() {
    __shared__ float2 s[256];
    int t = threadIdx.x;
    int col = blockIdx.x;
    for (int k = t; k < 256; k += 64)
        s[k] = make_float2(k == col ? 1.f : 0.f, 0.f);

    for (int g = 0; g < 17; g++) {
        float2 g4[4][4];
        const float2* Gp = &g_G[g][0];
#pragma unroll
        for (int r = 0; r < 4; r++)
#pragma unroll
            for (int c = 0; c < 4; c++) g4[r][c] = Gp[r * 4 + c];
        apply2(s, g4, c_gwa[g], c_gwb[g], t);
    }
    __syncthreads();
    for (int k = t; k < 128; k += 64) {
        g_C[k * 256 + col]         = s[k + 128].x;
        g_C[(k + 128) * 256 + col] = s[k + 128].y;
    }
}

// ---------------- K3: M = I - 2 C^T C (64 blocks, 32x32 tiles, 2x2/thread) --------
__global__ __launch_bounds__(256) void msyrk_kernel() {
    int bi = (blockIdx.x >> 3) * 32, bj = (blockIdx.x & 7) * 32;
    __shared__ float As[32][33], Bs[32][33];
    int tx = threadIdx.x & 15, ty = threadIdx.x >> 4;
    float a00 = 0.f, a01 = 0.f, a10 = 0.f, a11 = 0.f;

    for (int k0 = 0; k0 < 256; k0 += 32) {
        for (int idx = threadIdx.x; idx < 1024; idx += 256) {
            int r = idx >> 5, c = idx & 31;
            As[r][c] = g_C[(k0 + r) * 256 + bi + c];
            Bs[r][c] = g_C[(k0 + r) * 256 + bj + c];
        }
        __syncthreads();
#pragma unroll
        for (int kk = 0; kk < 32; kk++) {
            float a0 = As[kk][ty * 2], a1 = As[kk][ty * 2 + 1];
            float b0 = Bs[kk][tx * 2], b1 = Bs[kk][tx * 2 + 1];
            a00 = fmaf(a0, b0, a00); a01 = fmaf(a0, b1, a01);
            a10 = fmaf(a1, b0, a10); a11 = fmaf(a1, b1, a11);
        }
        __syncthreads();
    }
    int gi = bi + ty * 2, gj = bj + tx * 2;
    g_M[gi * 256 + gj]           = (gi == gj ? 1.f : 0.f) - 2.f * a00;
    g_M[gi * 256 + gj + 1]       = (gi == gj + 1 ? 1.f : 0.f) - 2.f * a01;
    g_M[(gi + 1) * 256 + gj]     = (gi + 1 == gj ? 1.f : 0.f) - 2.f * a10;
    g_M[(gi + 1) * 256 + gj + 1] = (gi == gj ? 1.f : 0.f) - 2.f * a11;
}

// ---------------- K4: M -> T. 9 blocks: digits (p0,p1) fused from gmem ----------
__device__ __forceinline__ void pdec(int p, int* r, int* c, float* sg) {
    if (p == 2) { r[0] = 0; c[0] = 1; r[1] = 1; c[1] = 0; sg[0] = 1.f; sg[1] = 1.f; }
    else        { r[0] = 0; c[0] = 0; r[1] = 1; c[1] = 1; sg[0] = 1.f; sg[1] = (p == 0 ? 1.f : -1.f); }
}

__global__ __launch_bounds__(256) void pauli_kernel() {
    __shared__ float S[4096];
    int t = threadIdx.x;
    int p0 = blockIdx.x / 3, p1 = blockIdx.x % 3;
    int r0[2], c0[2], r1[2], c1[2];
    float s0[2], s1[2];
    pdec(p0, r0, c0, s0);
    pdec(p1, r1, c1, s1);

    for (int o = t; o < 4096; o += 256) {
        int i = o >> 6, j = o & 63;
        float v = 0.f;
#pragma unroll
        for (int t0 = 0; t0 < 2; t0++)
#pragma unroll
            for (int t1 = 0; t1 < 2; t1++)
                v += s0[t0] * s1[t1] *
                     g_M[(i + 128 * r0[t0] + 64 * r1[t1]) * 256 +
                         (j + 128 * c0[t0] + 64 * c1[t1])];
        S[o] = v;
    }
    __syncthreads();

    int nc = 1;
    for (int d = 2; d < 8; d++) {
        int sh = 7 - d;
        int half = 1 << sh;
        int hh = half * half;
        int n_out = nc * 3 * hh;
        int in_blk = 4 * hh;
        int full = half << 1;
        float reg[12];
#pragma unroll
        for (int u = 0; u < 12; u++) {
            int o = t + (u << 8);
            if (o < n_out) {
                int j = o & (half - 1);
                int rr = o >> sh;
                int i = rr & (half - 1);
                int r2 = rr >> sh;
                int p = r2 % 3;
                int c = r2 / 3;
                const float* base = S + c * in_blk;
                float v;
                if (p == 0)      v = base[i * full + j] + base[(i + half) * full + j + half];
                else if (p == 1) v = base[i * full + j] - base[(i + half) * full + j + half];
                else             v = base[i * full + j + half] + base[(i + half) * full + j];
                reg[u] = v;
            }
        }
        __syncthreads();
#pragma unroll
        for (int u = 0; u < 12; u++) {
            int o = t + (u << 8);
            if (o < n_out) S[o] = reg[u];
        }
        __syncthreads();
        nc *= 3;
    }
    for (int o = t; o < 729; o += 256)
        g_T[blockIdx.x * 729 + o] = S[o];
}

// ---------------- K5: qval = a^T T b / 256; logits ----------------
__device__ __forceinline__ float selt(int d, float c, float s) {
    return d == 0 ? 1.f : (d == 1 ? c : s);
}

__global__ __launch_bounds__(256) void logits_kernel(const float* __restrict__ out_w,
                                                     const float* __restrict__ out_b,
                                                     float* __restrict__ out) {
    extern __shared__ float sm[];
    float* Tsh = sm;                 // 81*84
    float* ash = Tsh + 81 * 84;      // 64*84
    float* bsh = ash + 64 * 84;      // 64*84
    float* qps = bsh + 64 * 84;      // 64*16
    float* qvs = qps + 64 * 16;      // 64

    int t = threadIdx.x;
    for (int i = t; i < 81 * 84; i += 256) Tsh[i] = 0.f;
    for (int i = t; i < 64 * 84; i += 256) bsh[i] = 0.f;
    __syncthreads();
    for (int i = t; i < 6561; i += 256) Tsh[(i / 81) * 84 + (i % 81)] = g_T[i];

    {
        int s = t >> 2, part = t & 3;
        int sg = blockIdx.x * 64 + s;
        float tc[8], ts[8];
#pragma unroll
        for (int w = 0; w < 8; w++) {
            float f = g_feats[sg * 8 + w];
            __sincosf(f, &ts[w], &tc[w]);
        }
        int m0 = part * 21;
        int m1 = m0 + 21; if (m1 > 81) m1 = 81;
        for (int m = m0; m < m1; m++) {
            int d0 = m / 27, d1 = (m / 9) % 3, d2 = (m / 3) % 3, d3 = m % 3;
            ash[s * 84 + m] = selt(d0, tc[0], ts[0]) * selt(d1, tc[1], ts[1]) *
                              selt(d2, tc[2], ts[2]) * selt(d3, tc[3], ts[3]);
            bsh[s * 84 + m] = selt(d0, tc[4], ts[4]) * selt(d1, tc[5], ts[5]) *
                              selt(d2, tc[6], ts[6]) * selt(d3, tc[7], ts[7]);
        }
    }
    __syncthreads();

    if (t < 224) {
        int sg = t / 14, ng = t % 14;
        int s0 = sg * 4, n0 = ng * 6;
        float e[4][6];
#pragma unroll
        for (int i = 0; i < 4; i++)
#pragma unroll
            for (int j = 0; j < 6; j++) e[i][j] = 0.f;
        for (int m = 0; m < 81; m++) {
            float tv[6];
#pragma unroll
            for (int j = 0; j < 6; j++) tv[j] = Tsh[m * 84 + n0 + j];
#pragma unroll
            for (int i = 0; i < 4; i++) {
                float av = ash[(s0 + i) * 84 + m];
#pragma unroll
                for (int j = 0; j < 6; j++) e[i][j] = fmaf(av, tv[j], e[i][j]);
            }
        }
#pragma unroll
        for (int i = 0; i < 4; i++) {
            float q = 0.f;
#pragma unroll
            for (int j = 0; j < 6; j++) q += e[i][j] * bsh[(s0 + i) * 84 + n0 + j];
            qps[(s0 + i) * 16 + ng] = q;
        }
    }
    __syncthreads();
    if (t < 64) {
        float q = 0.f;
#pragma unroll
        for (int k = 0; k < 14; k++) q += qps[t * 16 + k];
        qvs[t] = q * (1.0f / 256.0f);
    }
    __syncthreads();
    for (int i = t; i < 640; i += 256) {
        int s = i / 10, c = i % 10;
        out[(blockIdx.x * 64 + s) * 10 + c] = qvs[s] * out_w[c] + out_b[c];
    }
}

// ---------------- launch: feats FIRST (clock soak), then chain, then logits ----
extern "C" void kernel_launch(void* const* d_in, const int* in_sizes, int n_in,
                              void* d_out, int out_size) {
    const float* x     = (const float*)d_in[0];
    const float* fcw   = (const float*)d_in[1];
    const float* fcb   = (const float*)d_in[2];
    const float* conv  = (const float*)d_in[3];
    const float* pool  = (const float*)d_in[4];
    const float* last  = (const float*)d_in[5];
    const float* out_w = (const float*)d_in[6];
    const float* out_b = (const float*)d_in[7];
    float* out = (float*)d_out;

    static bool inited = false;
    if (!inited) {
        cudaFuncSetAttribute(feats_kernel, cudaFuncAttributeMaxDynamicSharedMemorySize, 8 * 3072 * 4);
        cudaFuncSetAttribute(logits_kernel, cudaFuncAttributeMaxDynamicSharedMemorySize, 18644 * 4);
        inited = true;
    }

    feats_kernel<<<256, 512, 8 * 3072 * 4>>>(x, fcw, fcb);
    gates_kernel<<<1, 32>>>(conv, pool, last);
    circuit_kernel<<<256, 64>>>();
    msyrk_kernel<<<64, 256>>>();
    pauli_kernel<<<9, 256>>>();
    logits_kernel<<<128, 256, 18644 * 4>>>(out_w, out_b, out);
}

// round 13
// speedup vs baseline: 1.0314x; 1.0237x over previous
#include <cuda_runtime.h>
#include <math.h>

// ---------------- scratch (device globals, no allocation) ----------------
__device__ float g_feats[8192 * 8];
__device__ float g_C[256 * 256];   // rows 0-127: Re(U[128:256,:]), rows 128-255: Im
__device__ float g_M[256 * 256];
__device__ float g_T[6561];
__device__ float2 g_G[17][16];

// grid barrier state (zero-init; gen monotonic across replays, cnt returns to 0)
__device__ volatile unsigned g_bar_gen;
__device__ unsigned g_bar_cnt;

#define MEGA_BLOCKS 128
#define MEGA_SMEM_FLOATS 18656
#define MEGA_SMEM_BYTES (MEGA_SMEM_FLOATS * 4)

__device__ __forceinline__ void grid_bar() {
    __syncthreads();
    if (threadIdx.x == 0) {
        __threadfence();
        unsigned gen = g_bar_gen;
        if (atomicAdd(&g_bar_cnt, 1u) == MEGA_BLOCKS - 1u) {
            g_bar_cnt = 0;
            __threadfence();
            g_bar_gen = gen + 1u;
        } else {
            while (g_bar_gen == gen) { __nanosleep(64); }
        }
        __threadfence();
    }
    __syncthreads();
}

// ---------------- complex helpers ----------------
__device__ __forceinline__ float2 cmul(float2 a, float2 b) {
    return make_float2(a.x * b.x - a.y * b.y, a.x * b.y + a.y * b.x);
}
__device__ __forceinline__ float2 cadd(float2 a, float2 b) {
    return make_float2(a.x + b.x, a.y + b.y);
}

__constant__ float2 c_P[4][2][2] = {
    { { {1.f,0.f},{0.f,0.f} }, { {0.f,0.f},{1.f,0.f} } },   // I
    { { {0.f,0.f},{1.f,0.f} }, { {1.f,0.f},{0.f,0.f} } },   // X
    { { {0.f,0.f},{0.f,-1.f} }, { {0.f,1.f},{0.f,0.f} } },  // Y
    { { {1.f,0.f},{0.f,0.f} }, { {0.f,0.f},{-1.f,0.f} } },  // Z
};

__constant__ int c_gwa[17] = {0,2,4,6,1,3,5, 1,3,5,7, 0,4,2, 2,6, 0};
__constant__ int c_gwb[17] = {1,3,5,7,2,4,6, 0,2,4,6, 2,6,4, 0,4, 4};

// ---------------- K1: feats = tanh(x @ fc_w^T + fc_b) ----------------
__global__ __launch_bounds__(512, 2) void feats_kernel(const float* __restrict__ x,
                                                       const float* __restrict__ fcw,
                                                       const float* __restrict__ fcb) {
    extern __shared__ float wsh[];  // 96KB
    int tid = threadIdx.x;
    for (int i = tid * 4; i < 8 * 3072; i += 512 * 4)
        *(float4*)&wsh[i] = *(const float4*)&fcw[i];
    __syncthreads();

    int warp = tid >> 5, lane = tid & 31;
    long long row0 = ((long long)blockIdx.x * 16 + warp) * 2;  // 0..8190

    float acc[8][2];
#pragma unroll
    for (int q = 0; q < 8; q++) { acc[q][0] = 0.f; acc[q][1] = 0.f; }

#pragma unroll 4
    for (int it = 0; it < 24; it++) {
        int c = (it * 32 + lane) * 4;
        float4 xv0 = *(const float4*)&x[row0 * 3072 + c];
        float4 xv1 = *(const float4*)&x[(row0 + 1) * 3072 + c];
#pragma unroll
        for (int q = 0; q < 8; q++) {
            float4 wv = *(const float4*)&wsh[q * 3072 + c];
            acc[q][0] += wv.x * xv0.x + wv.y * xv0.y + wv.z * xv0.z + wv.w * xv0.w;
            acc[q][1] += wv.x * xv1.x + wv.y * xv1.y + wv.z * xv1.z + wv.w * xv1.w;
        }
    }
#pragma unroll
    for (int q = 0; q < 8; q++) {
#pragma unroll
        for (int r = 0; r < 2; r++) {
            float v = acc[q][r];
            v += __shfl_down_sync(0xffffffffu, v, 16);
            v += __shfl_down_sync(0xffffffffu, v, 8);
            v += __shfl_down_sync(0xffffffffu, v, 4);
            v += __shfl_down_sync(0xffffffffu, v, 2);
            v += __shfl_down_sync(0xffffffffu, v, 1);
            if (lane == 0) g_feats[(row0 + r) * 8 + q] = tanhf(v + fcb[q]);
        }
    }
}

// ---------------- gate-construction helpers ----------------
__device__ __forceinline__ void u3g(float th, float ph, float dl, float2 g[2][2]) {
    float st, ct; __sincosf(0.5f * th, &st, &ct);
    float sp, cp; __sincosf(ph, &sp, &cp);
    float sd, cd; __sincosf(dl, &sd, &cd);
    float spd, cpd; __sincosf(ph + dl, &spd, &cpd);
    g[0][0] = make_float2(ct, 0.f);
    g[0][1] = make_float2(-cd * st, -sd * st);
    g[1][0] = make_float2(cp * st, sp * st);
    g[1][1] = make_float2(cpd * ct, spd * ct);
}

__device__ __forceinline__ void zero4(float2 g[4][4]) {
#pragma unroll
    for (int r = 0; r < 4; r++)
#pragma unroll
        for (int c = 0; c < 4; c++) g[r][c] = make_float2(0.f, 0.f);
}

__device__ __forceinline__ void kron22(const float2 A[2][2], const float2 B[2][2],
                                       float2 P[4][4]) {
#pragma unroll
    for (int ra = 0; ra < 2; ra++)
#pragma unroll
        for (int rb = 0; rb < 2; rb++)
#pragma unroll
            for (int ca = 0; ca < 2; ca++)
#pragma unroll
                for (int cb = 0; cb < 2; cb++)
                    P[ra * 2 + rb][ca * 2 + cb] = cmul(A[ra][ca], B[rb][cb]);
}

__device__ __forceinline__ void mm4(const float2 A[4][4], const float2 B[4][4],
                                    float2 C[4][4]) {
#pragma unroll
    for (int i = 0; i < 4; i++)
#pragma unroll
        for (int j = 0; j < 4; j++) {
            float2 s = make_float2(0.f, 0.f);
#pragma unroll
            for (int k = 0; k < 4; k++) s = cadd(s, cmul(A[i][k], B[k][j]));
            C[i][j] = s;
        }
}

__device__ __forceinline__ float selt(int d, float c, float s) {
    return d == 0 ? 1.f : (d == 1 ? c : s);
}

__device__ __forceinline__ void pdec(int p, int* r, int* c, float* sg) {
    if (p == 2) { r[0] = 0; c[0] = 1; r[1] = 1; c[1] = 0; sg[0] = 1.f; sg[1] = 1.f; }
    else        { r[0] = 0; c[0] = 0; r[1] = 1; c[1] = 1; sg[0] = 1.f; sg[1] = (p == 0 ? 1.f : -1.f); }
}

// ---------------- mega kernel: gates -> circuit -> msyrk -> pauli -> logits ----
__global__ __launch_bounds__(256) void mega_kernel(const float* __restrict__ conv,
                                                   const float* __restrict__ pool,
                                                   const float* __restrict__ last,
                                                   const float* __restrict__ out_w,
                                                   const float* __restrict__ out_b,
                                                   float* __restrict__ out) {
    extern __shared__ __align__(16) float SM[];
    int t = threadIdx.x;
    int b = blockIdx.x;

    // ============ stage 0: gates (block 0, warp 0) ============
    if (b == 0 && t < 32) {
        float2 (*Psh)[16] = (float2(*)[16])SM;
        int g = t;
        if (g < 16) {
            float2 G[4][4];
            bool is_conv = (g <= 6) || (g >= 11 && g <= 13);
            if (is_conv) {
                int layer, idx;
                if (g <= 6) { const int ii[7] = {0, 2, 4, 6, 1, 3, 5}; layer = 0; idx = ii[g]; }
                else        { const int ii[3] = {0, 2, 1};             layer = 1; idx = ii[g - 11]; }
                const float* cw = conv + layer * 8 * 15;
                float2 A1[2][2], B1[2][2], A2[2][2], B2[2][2];
                u3g(cw[idx * 15 + 0], cw[idx * 15 + 1], cw[idx * 15 + 2], A1);
                u3g(cw[(idx + 1) * 15 + 3], cw[(idx + 1) * 15 + 4], cw[(idx + 1) * 15 + 5], B1);
                u3g(cw[idx * 15 + 9], cw[idx * 15 + 10], cw[idx * 15 + 11], A2);
                u3g(cw[(idx + 1) * 15 + 12], cw[(idx + 1) * 15 + 13], cw[(idx + 1) * 15 + 14], B2);
                float2 P1[4][4], P2[4][4], T1[4][4], T2[4][4], IS[4][4];
                kron22(A1, B1, P1);
                kron22(A2, B2, P2);
                { // ZZ
                    float sn, cs; __sincosf(0.5f * cw[idx * 15 + 6], &sn, &cs);
                    zero4(IS);
                    IS[0][0] = make_float2(cs, -sn);
                    IS[1][1] = make_float2(cs, sn);
                    IS[2][2] = make_float2(cs, sn);
                    IS[3][3] = make_float2(cs, -sn);
                    mm4(IS, P1, T1);
                }
                { // YY
                    float sn, cs; __sincosf(0.5f * cw[idx * 15 + 7], &sn, &cs);
                    zero4(IS);
                    IS[0][0] = IS[1][1] = IS[2][2] = IS[3][3] = make_float2(cs, 0.f);
                    IS[0][3] = make_float2(0.f, sn);
                    IS[1][2] = make_float2(0.f, -sn);
                    IS[2][1] = make_float2(0.f, -sn);
                    IS[3][0] = make_float2(0.f, sn);
                    mm4(IS, T1, T2);
                }
                { // XX
                    float sn, cs; __sincosf(0.5f * cw[idx * 15 + 8], &sn, &cs);
                    zero4(IS);
                    IS[0][0] = IS[1][1] = IS[2][2] = IS[3][3] = make_float2(cs, 0.f);
                    IS[0][3] = IS[1][2] = IS[2][1] = IS[3][0] = make_float2(0.f, -sn);
                    mm4(IS, T2, T1);
                }
                mm4(P2, T1, G);
            } else {
                int layer = (g <= 10) ? 0 : 1;
                int pi = (g <= 10) ? (g - 7) : (g - 14);
                const float* pw = pool + layer * 4 * 3;
                float2 u[2][2];
                u3g(pw[pi * 3 + 0], pw[pi * 3 + 1], pw[pi * 3 + 2], u);
                zero4(G);
                G[0][0] = make_float2(1.f, 0.f);
                G[1][1] = make_float2(1.f, 0.f);
                G[2][2] = u[0][0]; G[2][3] = u[0][1];
                G[3][2] = u[1][0]; G[3][3] = u[1][1];
            }
#pragma unroll
            for (int r = 0; r < 4; r++)
#pragma unroll
                for (int c = 0; c < 4; c++) g_G[g][r * 4 + c] = G[r][c];
        }
        // gate 16: tree product of 15 Pauli rotations
        {
            float2 Mk[4][4];
            if (g < 15) {
                int pa = (g + 1) >> 2, pb = (g + 1) & 3;
                float sn, cs; __sincosf(0.5f * last[g], &sn, &cs);
#pragma unroll
                for (int r = 0; r < 4; r++)
#pragma unroll
                    for (int c = 0; c < 4; c++) {
                        float2 p2 = cmul(c_P[pa][r >> 1][c >> 1], c_P[pb][r & 1][c & 1]);
                        Mk[r][c] = make_float2((r == c ? cs : 0.f) + sn * p2.y, -sn * p2.x);
                    }
            } else {
                zero4(Mk);
#pragma unroll
                for (int i = 0; i < 4; i++) Mk[i][i] = make_float2(1.f, 0.f);
            }
            if (g < 16) {
#pragma unroll
                for (int r = 0; r < 4; r++)
#pragma unroll
                    for (int c = 0; c < 4; c++) Psh[g][r * 4 + c] = Mk[r][c];
            }
            __syncwarp();
            for (int cnt = 8; cnt >= 1; cnt >>= 1) {
                if (g < cnt) {
                    float2 A[4][4], B[4][4], R[4][4];
#pragma unroll
                    for (int r = 0; r < 4; r++)
#pragma unroll
                        for (int c = 0; c < 4; c++) {
                            A[r][c] = Psh[2 * g + 1][r * 4 + c];
                            B[r][c] = Psh[2 * g][r * 4 + c];
                        }
                    mm4(A, B, R);
                    __syncwarp(0xffffffffu >> (32 - cnt));
#pragma unroll
                    for (int r = 0; r < 4; r++)
#pragma unroll
                        for (int c = 0; c < 4; c++) Psh[g][r * 4 + c] = R[r][c];
                }
                __syncwarp();
            }
            if (g == 0) {
#pragma unroll
                for (int r = 0; r < 4; r++)
#pragma unroll
                    for (int c = 0; c < 4; c++) g_G[16][r * 4 + c] = Psh[0][r * 4 + c];
            }
        }
    }
    grid_bar();

    // ============ stage 1: circuit — 2 columns per block ============
    {
        int slot = t >> 7, tc = t & 127;
        int col = b * 2 + slot;
        float2* s = ((float2*)SM) + slot * 256;
        for (int k = tc; k < 256; k += 128)
            s[k] = make_float2(k == col ? 1.f : 0.f, 0.f);

        for (int g = 0; g < 17; g++) {
            float2 g4[4][4];
            const float2* Gp = &g_G[g][0];
#pragma unroll
            for (int r = 0; r < 4; r++)
#pragma unroll
                for (int c = 0; c < 4; c++) g4[r][c] = Gp[r * 4 + c];
            __syncthreads();
            if (tc < 64) {
                int wa = c_gwa[g], wb = c_gwb[g];
                int ma = 1 << (7 - wa), mb = 1 << (7 - wb);
                int lo = ma < mb ? ma : mb;
                int hi = ma < mb ? mb : ma;
                int k = tc;
                k = ((k & ~(lo - 1)) << 1) | (k & (lo - 1));
                k = ((k & ~(hi - 1)) << 1) | (k & (hi - 1));
                int i0 = k, i1 = k | mb, i2 = k | ma, i3 = k | ma | mb;
                float2 v0 = s[i0], v1 = s[i1], v2 = s[i2], v3 = s[i3];
                float2 o0 = cadd(cadd(cmul(g4[0][0], v0), cmul(g4[0][1], v1)),
                                 cadd(cmul(g4[0][2], v2), cmul(g4[0][3], v3)));
                float2 o1 = cadd(cadd(cmul(g4[1][0], v0), cmul(g4[1][1], v1)),
                                 cadd(cmul(g4[1][2], v2), cmul(g4[1][3], v3)));
                float2 o2 = cadd(cadd(cmul(g4[2][0], v0), cmul(g4[2][1], v1)),
                                 cadd(cmul(g4[2][2], v2), cmul(g4[2][3], v3)));
                float2 o3 = cadd(cadd(cmul(g4[3][0], v0), cmul(g4[3][1], v1)),
                                 cadd(cmul(g4[3][2], v2), cmul(g4[3][3], v3)));
                s[i0] = o0; s[i1] = o1; s[i2] = o2; s[i3] = o3;
            }
        }
        __syncthreads();
        // store bottom half rows: C = [Re; Im]
        {
            int k = tc;  // 0..127
            g_C[k * 256 + col]         = s[k + 128].x;
            g_C[(k + 128) * 256 + col] = s[k + 128].y;
        }
    }
    grid_bar();

    // ============ stage 2: msyrk (blocks 0..63) ============
    if (b < 64) {
        float (*As)[33] = (float(*)[33])SM;
        float (*Bs)[33] = (float(*)[33])(SM + 32 * 33);
        int bi = (b >> 3) * 32, bj = (b & 7) * 32;
        int tx = t & 15, ty = t >> 4;
        float a00 = 0.f, a01 = 0.f, a10 = 0.f, a11 = 0.f;

        for (int k0 = 0; k0 < 256; k0 += 32) {
            __syncthreads();
            for (int idx = t; idx < 1024; idx += 256) {
                int r = idx >> 5, c = idx & 31;
                As[r][c] = g_C[(k0 + r) * 256 + bi + c];
                Bs[r][c] = g_C[(k0 + r) * 256 + bj + c];
            }
            __syncthreads();
#pragma unroll
            for (int kk = 0; kk < 32; kk++) {
                float a0 = As[kk][ty * 2], a1 = As[kk][ty * 2 + 1];
                float b0 = Bs[kk][tx * 2], b1 = Bs[kk][tx * 2 + 1];
                a00 = fmaf(a0, b0, a00); a01 = fmaf(a0, b1, a01);
                a10 = fmaf(a1, b0, a10); a11 = fmaf(a1, b1, a11);
            }
        }
        int gi = bi + ty * 2, gj = bj + tx * 2;
        g_M[gi * 256 + gj]           = (gi == gj ? 1.f : 0.f) - 2.f * a00;
        g_M[gi * 256 + gj + 1]       = (gi == gj + 1 ? 1.f : 0.f) - 2.f * a01;
        g_M[(gi + 1) * 256 + gj]     = (gi + 1 == gj ? 1.f : 0.f) - 2.f * a10;
        g_M[(gi + 1) * 256 + gj + 1] = (gi == gj ? 1.f : 0.f) - 2.f * a11;
    }
    grid_bar();

    // ============ stage 3: pauli (blocks 0..8) ============
    if (b < 9) {
        float* S = SM;  // 4096 floats
        int p0 = b / 3, p1 = b % 3;
        int r0[2], c0[2], r1[2], c1[2];
        float s0[2], s1[2];
        pdec(p0, r0, c0, s0);
        pdec(p1, r1, c1, s1);

        __syncthreads();
        for (int o = t; o < 4096; o += 256) {
            int i = o >> 6, j = o & 63;
            float v = 0.f;
#pragma unroll
            for (int t0 = 0; t0 < 2; t0++)
#pragma unroll
                for (int t1 = 0; t1 < 2; t1++)
                    v += s0[t0] * s1[t1] *
                         g_M[(i + 128 * r0[t0] + 64 * r1[t1]) * 256 +
                             (j + 128 * c0[t0] + 64 * c1[t1])];
            S[o] = v;
        }
        __syncthreads();

        int nc = 1;
        for (int d = 2; d < 8; d++) {
            int sh = 7 - d;
            int half = 1 << sh;
            int hh = half * half;
            int n_out = nc * 3 * hh;
            int in_blk = 4 * hh;
            int full = half << 1;
            float reg[12];
#pragma unroll
            for (int u = 0; u < 12; u++) {
                int o = t + (u << 8);
                if (o < n_out) {
                    int j = o & (half - 1);
                    int rr = o >> sh;
                    int i = rr & (half - 1);
                    int r2 = rr >> sh;
                    int p = r2 % 3;
                    int c = r2 / 3;
                    const float* base = S + c * in_blk;
                    float v;
                    if (p == 0)      v = base[i * full + j] + base[(i + half) * full + j + half];
                    else if (p == 1) v = base[i * full + j] - base[(i + half) * full + j + half];
                    else             v = base[i * full + j + half] + base[(i + half) * full + j];
                    reg[u] = v;
                }
            }
            __syncthreads();
#pragma unroll
            for (int u = 0; u < 12; u++) {
                int o = t + (u << 8);
                if (o < n_out) S[o] = reg[u];
            }
            __syncthreads();
            nc *= 3;
        }
        for (int o = t; o < 729; o += 256)
            g_T[b * 729 + o] = S[o];
    }
    grid_bar();

    // ============ stage 4: logits (all 128 blocks, 64 samples each) ============
    {
        float* Tsh = SM;                 // 81*84 = 6804
        float* ash = Tsh + 81 * 84;      // 64*84
        float* bsh = ash + 64 * 84;      // 64*84
        float* qps = bsh + 64 * 84;      // 64*16
        float* qvs = qps + 64 * 16;      // 64

        __syncthreads();
        for (int i = t; i < 81 * 84; i += 256) Tsh[i] = 0.f;
        for (int i = t; i < 64 * 84; i += 256) bsh[i] = 0.f;
        __syncthreads();
        for (int i = t; i < 6561; i += 256) Tsh[(i / 81) * 84 + (i % 81)] = g_T[i];

        {
            int s = t >> 2, part = t & 3;
            int sg = b * 64 + s;
            float tc8[8], ts8[8];
#pragma unroll
            for (int w = 0; w < 8; w++) {
                float f = g_feats[sg * 8 + w];
                __sincosf(f, &ts8[w], &tc8[w]);
            }
            int m0 = part * 21;
            int m1 = m0 + 21; if (m1 > 81) m1 = 81;
            for (int m = m0; m < m1; m++) {
                int d0 = m / 27, d1 = (m / 9) % 3, d2 = (m / 3) % 3, d3 = m % 3;
                ash[s * 84 + m] = selt(d0, tc8[0], ts8[0]) * selt(d1, tc8[1], ts8[1]) *
                                  selt(d2, tc8[2], ts8[2]) * selt(d3, tc8[3], ts8[3]);
                bsh[s * 84 + m] = selt(d0, tc8[4], ts8[4]) * selt(d1, tc8[5], ts8[5]) *
                                  selt(d2, tc8[6], ts8[6]) * selt(d3, tc8[7], ts8[7]);
            }
        }
        __syncthreads();

        if (t < 224) {
            int sg2 = t / 14, ng = t % 14;
            int s0 = sg2 * 4, n0 = ng * 6;
            float e[4][6];
#pragma unroll
            for (int i = 0; i < 4; i++)
#pragma unroll
                for (int j = 0; j < 6; j++) e[i][j] = 0.f;
            for (int m = 0; m < 81; m++) {
                float tv[6];
#pragma unroll
                for (int j = 0; j < 6; j++) tv[j] = Tsh[m * 84 + n0 + j];
#pragma unroll
                for (int i = 0; i < 4; i++) {
                    float av = ash[(s0 + i) * 84 + m];
#pragma unroll
                    for (int j = 0; j < 6; j++) e[i][j] = fmaf(av, tv[j], e[i][j]);
                }
            }
#pragma unroll
            for (int i = 0; i < 4; i++) {
                float q = 0.f;
#pragma unroll
                for (int j = 0; j < 6; j++) q += e[i][j] * bsh[(s0 + i) * 84 + n0 + j];
                qps[(s0 + i) * 16 + ng] = q;
            }
        }
        __syncthreads();
        if (t < 64) {
            float q = 0.f;
#pragma unroll
            for (int k = 0; k < 14; k++) q += qps[t * 16 + k];
            qvs[t] = q * (1.0f / 256.0f);
        }
        __syncthreads();
        for (int i = t; i < 640; i += 256) {
            int s = i / 10, c = i % 10;
            out[(b * 64 + s) * 10 + c] = qvs[s] * out_w[c] + out_b[c];
        }
    }
}

// ---------------- launch: 2 kernels total ----------------
extern "C" void kernel_launch(void* const* d_in, const int* in_sizes, int n_in,
                              void* d_out, int out_size) {
    const float* x     = (const float*)d_in[0];
    const float* fcw   = (const float*)d_in[1];
    const float* fcb   = (const float*)d_in[2];
    const float* conv  = (const float*)d_in[3];
    const float* pool  = (const float*)d_in[4];
    const float* last  = (const float*)d_in[5];
    const float* out_w = (const float*)d_in[6];
    const float* out_b = (const float*)d_in[7];
    float* out = (float*)d_out;

    static bool inited = false;
    if (!inited) {
        cudaFuncSetAttribute(feats_kernel, cudaFuncAttributeMaxDynamicSharedMemorySize, 8 * 3072 * 4);
        cudaFuncSetAttribute(mega_kernel, cudaFuncAttributeMaxDynamicSharedMemorySize, MEGA_SMEM_BYTES);
        inited = true;
    }

    feats_kernel<<<256, 512, 8 * 3072 * 4>>>(x, fcw, fcb);
    mega_kernel<<<MEGA_BLOCKS, 256, MEGA_SMEM_BYTES>>>(conv, pool, last, out_w, out_b, out);
}

// round 15
// speedup vs baseline: 1.1356x; 1.1010x over previous
#include <cuda_runtime.h>
#include <math.h>

// ---------------- scratch (device globals, no allocation) ----------------
__device__ float g_feats[8192 * 8];
__device__ float g_C[256 * 256];   // rows 0-127: Re(U[128:256,:]), rows 128-255: Im
__device__ float g_M[256 * 256];
__device__ float g_T[6561];

// grid barrier state (zero-init; gen monotonic across replays, cnt returns to 0)
__device__ volatile unsigned g_bar_gen;
__device__ unsigned g_bar_cnt;

#define MEGA_BLOCKS 128
#define MEGA_SMEM_FLOATS 18656
#define MEGA_SMEM_BYTES (MEGA_SMEM_FLOATS * 4)

__device__ __forceinline__ void grid_bar() {
    __syncthreads();
    if (threadIdx.x == 0) {
        __threadfence();
        unsigned gen = g_bar_gen;
        if (atomicAdd(&g_bar_cnt, 1u) == MEGA_BLOCKS - 1u) {
            g_bar_cnt = 0;
            __threadfence();
            g_bar_gen = gen + 1u;
        } else {
            while (g_bar_gen == gen) { }
        }
        __threadfence();
    }
    __syncthreads();
}

// ---------------- complex helpers ----------------
__device__ __forceinline__ float2 cmul(float2 a, float2 b) {
    return make_float2(a.x * b.x - a.y * b.y, a.x * b.y + a.y * b.x);
}
__device__ __forceinline__ float2 cadd(float2 a, float2 b) {
    return make_float2(a.x + b.x, a.y + b.y);
}

__constant__ float2 c_P[4][2][2] = {
    { { {1.f,0.f},{0.f,0.f} }, { {0.f,0.f},{1.f,0.f} } },   // I
    { { {0.f,0.f},{1.f,0.f} }, { {1.f,0.f},{0.f,0.f} } },   // X
    { { {0.f,0.f},{0.f,-1.f} }, { {0.f,1.f},{0.f,0.f} } },  // Y
    { { {1.f,0.f},{0.f,0.f} }, { {0.f,0.f},{-1.f,0.f} } },  // Z
};

__constant__ int c_gwa[17] = {0,2,4,6,1,3,5, 1,3,5,7, 0,4,2, 2,6, 0};
__constant__ int c_gwb[17] = {1,3,5,7,2,4,6, 0,2,4,6, 2,6,4, 0,4, 4};

// ---------------- K1: feats = tanh(x @ fc_w^T + fc_b) ----------------
__global__ __launch_bounds__(512, 2) void feats_kernel(const float* __restrict__ x,
                                                       const float* __restrict__ fcw,
                                                       const float* __restrict__ fcb) {
    extern __shared__ float wsh[];  // 96KB
    int tid = threadIdx.x;
    for (int i = tid * 4; i < 8 * 3072; i += 512 * 4)
        *(float4*)&wsh[i] = *(const float4*)&fcw[i];
    __syncthreads();

    int warp = tid >> 5, lane = tid & 31;
    long long row0 = ((long long)blockIdx.x * 16 + warp) * 2;  // 0..8190

    float acc[8][2];
#pragma unroll
    for (int q = 0; q < 8; q++) { acc[q][0] = 0.f; acc[q][1] = 0.f; }

#pragma unroll 4
    for (int it = 0; it < 24; it++) {
        int c = (it * 32 + lane) * 4;
        float4 xv0 = *(const float4*)&x[row0 * 3072 + c];
        float4 xv1 = *(const float4*)&x[(row0 + 1) * 3072 + c];
#pragma unroll
        for (int q = 0; q < 8; q++) {
            float4 wv = *(const float4*)&wsh[q * 3072 + c];
            acc[q][0] += wv.x * xv0.x + wv.y * xv0.y + wv.z * xv0.z + wv.w * xv0.w;
            acc[q][1] += wv.x * xv1.x + wv.y * xv1.y + wv.z * xv1.z + wv.w * xv1.w;
        }
    }
#pragma unroll
    for (int q = 0; q < 8; q++) {
#pragma unroll
        for (int r = 0; r < 2; r++) {
            float v = acc[q][r];
            v += __shfl_down_sync(0xffffffffu, v, 16);
            v += __shfl_down_sync(0xffffffffu, v, 8);
            v += __shfl_down_sync(0xffffffffu, v, 4);
            v += __shfl_down_sync(0xffffffffu, v, 2);
            v += __shfl_down_sync(0xffffffffu, v, 1);
            if (lane == 0) g_feats[(row0 + r) * 8 + q] = tanhf(v + fcb[q]);
        }
    }
}

// ---------------- gate-construction helpers ----------------
__device__ __forceinline__ void u3g(float th, float ph, float dl, float2 g[2][2]) {
    float st, ct; __sincosf(0.5f * th, &st, &ct);
    float sp, cp; __sincosf(ph, &sp, &cp);
    float sd, cd; __sincosf(dl, &sd, &cd);
    float spd, cpd; __sincosf(ph + dl, &spd, &cpd);
    g[0][0] = make_float2(ct, 0.f);
    g[0][1] = make_float2(-cd * st, -sd * st);
    g[1][0] = make_float2(cp * st, sp * st);
    g[1][1] = make_float2(cpd * ct, spd * ct);
}

__device__ __forceinline__ void zero4(float2 g[4][4]) {
#pragma unroll
    for (int r = 0; r < 4; r++)
#pragma unroll
        for (int c = 0; c < 4; c++) g[r][c] = make_float2(0.f, 0.f);
}

__device__ __forceinline__ void kron22(const float2 A[2][2], const float2 B[2][2],
                                       float2 P[4][4]) {
#pragma unroll
    for (int ra = 0; ra < 2; ra++)
#pragma unroll
        for (int rb = 0; rb < 2; rb++)
#pragma unroll
            for (int ca = 0; ca < 2; ca++)
#pragma unroll
                for (int cb = 0; cb < 2; cb++)
                    P[ra * 2 + rb][ca * 2 + cb] = cmul(A[ra][ca], B[rb][cb]);
}

__device__ __forceinline__ void mm4(const float2 A[4][4], const float2 B[4][4],
                                    float2 C[4][4]) {
#pragma unroll
    for (int i = 0; i < 4; i++)
#pragma unroll
        for (int j = 0; j < 4; j++) {
            float2 s = make_float2(0.f, 0.f);
#pragma unroll
            for (int k = 0; k < 4; k++) s = cadd(s, cmul(A[i][k], B[k][j]));
            C[i][j] = s;
        }
}

__device__ __forceinline__ float selt(int d, float c, float s) {
    return d == 0 ? 1.f : (d == 1 ? c : s);
}

__device__ __forceinline__ void pdec(int p, int* r, int* c, float* sg) {
    if (p == 2) { r[0] = 0; c[0] = 1; r[1] = 1; c[1] = 0; sg[0] = 1.f; sg[1] = 1.f; }
    else        { r[0] = 0; c[0] = 0; r[1] = 1; c[1] = 1; sg[0] = 1.f; sg[1] = (p == 0 ? 1.f : -1.f); }
}

// per-block gate build: warp 0 fills Gsh[17][16]; Psh is 16x16 float2 workspace
__device__ void build_gates(const float* __restrict__ conv,
                            const float* __restrict__ pool,
                            const float* __restrict__ last,
                            float2* Gsh, float2 (*Psh)[16], int g) {
    if (g < 16) {
        float2 G[4][4];
        bool is_conv = (g <= 6) || (g >= 11 && g <= 13);
        if (is_conv) {
            int layer, idx;
            if (g <= 6) { const int ii[7] = {0, 2, 4, 6, 1, 3, 5}; layer = 0; idx = ii[g]; }
            else        { const int ii[3] = {0, 2, 1};             layer = 1; idx = ii[g - 11]; }
            const float* cw = conv + layer * 8 * 15;
            float2 A1[2][2], B1[2][2], A2[2][2], B2[2][2];
            u3g(cw[idx * 15 + 0], cw[idx * 15 + 1], cw[idx * 15 + 2], A1);
            u3g(cw[(idx + 1) * 15 + 3], cw[(idx + 1) * 15 + 4], cw[(idx + 1) * 15 + 5], B1);
            u3g(cw[idx * 15 + 9], cw[idx * 15 + 10], cw[idx * 15 + 11], A2);
            u3g(cw[(idx + 1) * 15 + 12], cw[(idx + 1) * 15 + 13], cw[(idx + 1) * 15 + 14], B2);
            float2 P1[4][4], P2[4][4], T1[4][4], T2[4][4], IS[4][4];
            kron22(A1, B1, P1);
            kron22(A2, B2, P2);
            { // ZZ
                float sn, cs; __sincosf(0.5f * cw[idx * 15 + 6], &sn, &cs);
                zero4(IS);
                IS[0][0] = make_float2(cs, -sn);
                IS[1][1] = make_float2(cs, sn);
                IS[2][2] = make_float2(cs, sn);
                IS[3][3] = make_float2(cs, -sn);
                mm4(IS, P1, T1);
            }
            { // YY
                float sn, cs; __sincosf(0.5f * cw[idx * 15 + 7], &sn, &cs);
                zero4(IS);
                IS[0][0] = IS[1][1] = IS[2][2] = IS[3][3] = make_float2(cs, 0.f);
                IS[0][3] = make_float2(0.f, sn);
                IS[1][2] = make_float2(0.f, -sn);
                IS[2][1] = make_float2(0.f, -sn);
                IS[3][0] = make_float2(0.f, sn);
                mm4(IS, T1, T2);
            }
            { // XX
                float sn, cs; __sincosf(0.5f * cw[idx * 15 + 8], &sn, &cs);
                zero4(IS);
                IS[0][0] = IS[1][1] = IS[2][2] = IS[3][3] = make_float2(cs, 0.f);
                IS[0][3] = IS[1][2] = IS[2][1] = IS[3][0] = make_float2(0.f, -sn);
                mm4(IS, T2, T1);
            }
            mm4(P2, T1, G);
        } else {
            int layer = (g <= 10) ? 0 : 1;
            int pi = (g <= 10) ? (g - 7) : (g - 14);
            const float* pw = pool + layer * 4 * 3;
            float2 u[2][2];
            u3g(pw[pi * 3 + 0], pw[pi * 3 + 1], pw[pi * 3 + 2], u);
            zero4(G);
            G[0][0] = make_float2(1.f, 0.f);
            G[1][1] = make_float2(1.f, 0.f);
            G[2][2] = u[0][0]; G[2][3] = u[0][1];
            G[3][2] = u[1][0]; G[3][3] = u[1][1];
        }
#pragma unroll
        for (int r = 0; r < 4; r++)
#pragma unroll
            for (int c = 0; c < 4; c++) Gsh[g * 16 + r * 4 + c] = G[r][c];
    }
    // gate 16: tree product of 15 Pauli rotations (lane 15 = identity)
    {
        float2 Mk[4][4];
        if (g < 15) {
            int pa = (g + 1) >> 2, pb = (g + 1) & 3;
            float sn, cs; __sincosf(0.5f * last[g], &sn, &cs);
#pragma unroll
            for (int r = 0; r < 4; r++)
#pragma unroll
                for (int c = 0; c < 4; c++) {
                    float2 p2 = cmul(c_P[pa][r >> 1][c >> 1], c_P[pb][r & 1][c & 1]);
                    Mk[r][c] = make_float2((r == c ? cs : 0.f) + sn * p2.y, -sn * p2.x);
                }
        } else {
            zero4(Mk);
#pragma unroll
            for (int i = 0; i < 4; i++) Mk[i][i] = make_float2(1.f, 0.f);
        }
        if (g < 16) {
#pragma unroll
            for (int r = 0; r < 4; r++)
#pragma unroll
                for (int c = 0; c < 4; c++) Psh[g][r * 4 + c] = Mk[r][c];
        }
        __syncwarp();
        for (int cnt = 8; cnt >= 1; cnt >>= 1) {
            if (g < cnt) {
                float2 A[4][4], B[4][4], R[4][4];
#pragma unroll
                for (int r = 0; r < 4; r++)
#pragma unroll
                    for (int c = 0; c < 4; c++) {
                        A[r][c] = Psh[2 * g + 1][r * 4 + c];
                        B[r][c] = Psh[2 * g][r * 4 + c];
                    }
                mm4(A, B, R);
                __syncwarp(0xffffffffu >> (32 - cnt));
#pragma unroll
                for (int r = 0; r < 4; r++)
#pragma unroll
                    for (int c = 0; c < 4; c++) Psh[g][r * 4 + c] = R[r][c];
            }
            __syncwarp();
        }
        if (g == 0) {
#pragma unroll
            for (int r = 0; r < 4; r++)
#pragma unroll
                for (int c = 0; c < 4; c++) Gsh[16 * 16 + r * 4 + c] = Psh[0][r * 4 + c];
        }
    }
}

// ---------------- mega kernel: [gates] circuit -> msyrk -> pauli -> logits ----
__global__ __launch_bounds__(256) void mega_kernel(const float* __restrict__ conv,
                                                   const float* __restrict__ pool,
                                                   const float* __restrict__ last,
                                                   const float* __restrict__ out_w,
                                                   const float* __restrict__ out_b,
                                                   float* __restrict__ out) {
    extern __shared__ __align__(16) float SM[];
    int t = threadIdx.x;
    int b = blockIdx.x;

    // ============ stage 1: gates (per-block, warp 0) + circuit (2 cols/block) ====
    {
        // smem layout: state = SM[0..1023] (2 slots x 256 float2)
        //              Gsh   = SM[1024..1568)  (17*16 float2)
        //              Psh   = SM[1568..2592)  (16*16 float2)
        float2* Gsh = (float2*)(SM + 1024);
        float2 (*Psh)[16] = (float2(*)[16])(SM + 1568);

        int slot = t >> 7, tc = t & 127;
        int col = b * 2 + slot;
        float2* s = ((float2*)SM) + slot * 256;
        for (int k = tc; k < 256; k += 128)
            s[k] = make_float2(k == col ? 1.f : 0.f, 0.f);
        if (t < 32) build_gates(conv, pool, last, Gsh, Psh, t);
        __syncthreads();

        for (int g = 0; g < 17; g++) {
            float2 g4[4][4];
#pragma unroll
            for (int r = 0; r < 4; r++)
#pragma unroll
                for (int c = 0; c < 4; c++) g4[r][c] = Gsh[g * 16 + r * 4 + c];
            __syncthreads();
            if (tc < 64) {
                int wa = c_gwa[g], wb = c_gwb[g];
                int ma = 1 << (7 - wa), mb = 1 << (7 - wb);
                int lo = ma < mb ? ma : mb;
                int hi = ma < mb ? mb : ma;
                int k = tc;
                k = ((k & ~(lo - 1)) << 1) | (k & (lo - 1));
                k = ((k & ~(hi - 1)) << 1) | (k & (hi - 1));
                int i0 = k, i1 = k | mb, i2 = k | ma, i3 = k | ma | mb;
                float2 v0 = s[i0], v1 = s[i1], v2 = s[i2], v3 = s[i3];
                float2 o0 = cadd(cadd(cmul(g4[0][0], v0), cmul(g4[0][1], v1)),
                                 cadd(cmul(g4[0][2], v2), cmul(g4[0][3], v3)));
                float2 o1 = cadd(cadd(cmul(g4[1][0], v0), cmul(g4[1][1], v1)),
                                 cadd(cmul(g4[1][2], v2), cmul(g4[1][3], v3)));
                float2 o2 = cadd(cadd(cmul(g4[2][0], v0), cmul(g4[2][1], v1)),
                                 cadd(cmul(g4[2][2], v2), cmul(g4[2][3], v3)));
                float2 o3 = cadd(cadd(cmul(g4[3][0], v0), cmul(g4[3][1], v1)),
                                 cadd(cmul(g4[3][2], v2), cmul(g4[3][3], v3)));
                s[i0] = o0; s[i1] = o1; s[i2] = o2; s[i3] = o3;
            }
        }
        __syncthreads();
        // store bottom half rows: C = [Re; Im]
        {
            int k = tc;  // 0..127
            g_C[k * 256 + col]         = s[k + 128].x;
            g_C[(k + 128) * 256 + col] = s[k + 128].y;
        }
    }
    grid_bar();

    // ============ stage 2: msyrk (blocks 0..63) — one bulk smem load ============
    if (b < 64) {
        float* As = SM;           // 256 x 32
        float* Bs = SM + 8192;    // 256 x 32
        int bi = (b >> 3) * 32, bj = (b & 7) * 32;
        for (int idx = t * 4; idx < 8192; idx += 1024) {
            int k = idx >> 5, c = idx & 31;
            *(float4*)&As[idx] = *(const float4*)&g_C[k * 256 + bi + c];
            *(float4*)&Bs[idx] = *(const float4*)&g_C[k * 256 + bj + c];
        }
        __syncthreads();
        int tx = t & 15, ty = t >> 4;
        float a00 = 0.f, a01 = 0.f, a10 = 0.f, a11 = 0.f;
#pragma unroll 8
        for (int kk = 0; kk < 256; kk++) {
            float2 av = *(float2*)&As[kk * 32 + ty * 2];
            float2 bv = *(float2*)&Bs[kk * 32 + tx * 2];
            a00 = fmaf(av.x, bv.x, a00); a01 = fmaf(av.x, bv.y, a01);
            a10 = fmaf(av.y, bv.x, a10); a11 = fmaf(av.y, bv.y, a11);
        }
        int gi = bi + ty * 2, gj = bj + tx * 2;
        g_M[gi * 256 + gj]           = (gi == gj ? 1.f : 0.f) - 2.f * a00;
        g_M[gi * 256 + gj + 1]       = (gi == gj + 1 ? 1.f : 0.f) - 2.f * a01;
        g_M[(gi + 1) * 256 + gj]     = (gi + 1 == gj ? 1.f : 0.f) - 2.f * a10;
        g_M[(gi + 1) * 256 + gj + 1] = (gi == gj ? 1.f : 0.f) - 2.f * a11;
    }
    grid_bar();

    // ============ stage 3: pauli (blocks 0..8) ============
    if (b < 9) {
        float* S = SM;  // 4096 floats
        int p0 = b / 3, p1 = b % 3;
        int r0[2], c0[2], r1[2], c1[2];
        float s0[2], s1[2];
        pdec(p0, r0, c0, s0);
        pdec(p1, r1, c1, s1);

        for (int o = t; o < 4096; o += 256) {
            int i = o >> 6, j = o & 63;
            float v = 0.f;
#pragma unroll
            for (int t0 = 0; t0 < 2; t0++)
#pragma unroll
                for (int t1 = 0; t1 < 2; t1++)
                    v += s0[t0] * s1[t1] *
                         g_M[(i + 128 * r0[t0] + 64 * r1[t1]) * 256 +
                             (j + 128 * c0[t0] + 64 * c1[t1])];
            S[o] = v;
        }
        __syncthreads();

        int nc = 1;
        for (int d = 2; d < 8; d++) {
            int sh = 7 - d;
            int half = 1 << sh;
            int hh = half * half;
            int n_out = nc * 3 * hh;
            int in_blk = 4 * hh;
            int full = half << 1;
            float reg[12];
#pragma unroll
            for (int u = 0; u < 12; u++) {
                int o = t + (u << 8);
                if (o < n_out) {
                    int j = o & (half - 1);
                    int rr = o >> sh;
                    int i = rr & (half - 1);
                    int r2 = rr >> sh;
                    int p = r2 % 3;
                    int c = r2 / 3;
                    const float* base = S + c * in_blk;
                    float v;
                    if (p == 0)      v = base[i * full + j] + base[(i + half) * full + j + half];
                    else if (p == 1) v = base[i * full + j] - base[(i + half) * full + j + half];
                    else             v = base[i * full + j + half] + base[(i + half) * full + j];
                    reg[u] = v;
                }
            }
            __syncthreads();
#pragma unroll
            for (int u = 0; u < 12; u++) {
                int o = t + (u << 8);
                if (o < n_out) S[o] = reg[u];
            }
            __syncthreads();
            nc *= 3;
        }
        for (int o = t; o < 729; o += 256)
            g_T[b * 729 + o] = S[o];
    }
    grid_bar();

    // ============ stage 4: logits (all 128 blocks, 64 samples each) ============
    {
        float* Tsh = SM;                 // 81*84 = 6804
        float* ash = Tsh + 81 * 84;      // 64*84
        float* bsh = ash + 64 * 84;      // 64*84
        float* qps = bsh + 64 * 84;      // 64*16
        float* qvs = qps + 64 * 16;      // 64

        for (int i = t; i < 81 * 84; i += 256) Tsh[i] = 0.f;
        for (int i = t; i < 64 * 84; i += 256) bsh[i] = 0.f;
        __syncthreads();
        for (int i = t; i < 6561; i += 256) Tsh[(i / 81) * 84 + (i % 81)] = g_T[i];

        {
            int s = t >> 2, part = t & 3;
            int sg = b * 64 + s;
            float tc8[8], ts8[8];
#pragma unroll
            for (int w = 0; w < 8; w++) {
                float f = g_feats[sg * 8 + w];
                __sincosf(f, &ts8[w], &tc8[w]);
            }
            int m0 = part * 21;
            int m1 = m0 + 21; if (m1 > 81) m1 = 81;
            for (int m = m0; m < m1; m++) {
                int d0 = m / 27, d1 = (m / 9) % 3, d2 = (m / 3) % 3, d3 = m % 3;
                ash[s * 84 + m] = selt(d0, tc8[0], ts8[0]) * selt(d1, tc8[1], ts8[1]) *
                                  selt(d2, tc8[2], ts8[2]) * selt(d3, tc8[3], ts8[3]);
                bsh[s * 84 + m] = selt(d0, tc8[4], ts8[4]) * selt(d1, tc8[5], ts8[5]) *
                                  selt(d2, tc8[6], ts8[6]) * selt(d3, tc8[7], ts8[7]);
            }
        }
        __syncthreads();

        if (t < 224) {
            int sg2 = t / 14, ng = t % 14;
            int s0 = sg2 * 4, n0 = ng * 6;
            float e[4][6];
#pragma unroll
            for (int i = 0; i < 4; i++)
#pragma unroll
                for (int j = 0; j < 6; j++) e[i][j] = 0.f;
            for (int m = 0; m < 81; m++) {
                float tv[6];
#pragma unroll
                for (int j = 0; j < 6; j++) tv[j] = Tsh[m * 84 + n0 + j];
#pragma unroll
                for (int i = 0; i < 4; i++) {
                    float av = ash[(s0 + i) * 84 + m];
#pragma unroll
                    for (int j = 0; j < 6; j++) e[i][j] = fmaf(av, tv[j], e[i][j]);
                }
            }
#pragma unroll
            for (int i = 0; i < 4; i++) {
                float q = 0.f;
#pragma unroll
                for (int j = 0; j < 6; j++) q += e[i][j] * bsh[(s0 + i) * 84 + n0 + j];
                qps[(s0 + i) * 16 + ng] = q;
            }
        }
        __syncthreads();
        if (t < 64) {
            float q = 0.f;
#pragma unroll
            for (int k = 0; k < 14; k++) q += qps[t * 16 + k];
            qvs[t] = q * (1.0f / 256.0f);
        }
        __syncthreads();
        for (int i = t; i < 640; i += 256) {
            int s = i / 10, c = i % 10;
            out[(b * 64 + s) * 10 + c] = qvs[s] * out_w[c] + out_b[c];
        }
    }
}

// ---------------- launch: 2 kernels total ----------------
extern "C" void kernel_launch(void* const* d_in, const int* in_sizes, int n_in,
                              void* d_out, int out_size) {
    const float* x     = (const float*)d_in[0];
    const float* fcw   = (const float*)d_in[1];
    const float* fcb   = (const float*)d_in[2];
    const float* conv  = (const float*)d_in[3];
    const float* pool  = (const float*)d_in[4];
    const float* last  = (const float*)d_in[5];
    const float* out_w = (const float*)d_in[6];
    const float* out_b = (const float*)d_in[7];
    float* out = (float*)d_out;

    static bool inited = false;
    if (!inited) {
        cudaFuncSetAttribute(feats_kernel, cudaFuncAttributeMaxDynamicSharedMemorySize, 8 * 3072 * 4);
        cudaFuncSetAttribute(mega_kernel, cudaFuncAttributeMaxDynamicSharedMemorySize, MEGA_SMEM_BYTES);
        inited = true;
    }

    feats_kernel<<<256, 512, 8 * 3072 * 4>>>(x, fcw, fcb);
    mega_kernel<<<MEGA_BLOCKS, 256, MEGA_SMEM_BYTES>>>(conv, pool, last, out_w, out_b, out);
}

// round 16
// speedup vs baseline: 1.1636x; 1.0246x over previous
#include <cuda_runtime.h>
#include <math.h>

// ---------------- scratch (device globals, no allocation) ----------------
__device__ float g_feats[8192 * 8];
__device__ float g_Ct[256 * 256];  // g_Ct[col*256 + kk] = C[kk, col]; kk<128 Re(U[128+kk,col]), kk>=128 Im
__device__ float g_M[256 * 256];
__device__ float g_T[6561];

// grid barrier state (zero-init; gen monotonic across replays, cnt returns to 0)
__device__ volatile unsigned g_bar_gen;
__device__ unsigned g_bar_cnt;

#define NBLK 256
#define SMEM_FLOATS 18656
#define SMEM_BYTES (SMEM_FLOATS * 4)

__device__ __forceinline__ void grid_bar() {
    __syncthreads();
    if (threadIdx.x == 0) {
        __threadfence();
        unsigned gen = g_bar_gen;
        if (atomicAdd(&g_bar_cnt, 1u) == NBLK - 1u) {
            g_bar_cnt = 0;
            __threadfence();
            g_bar_gen = gen + 1u;
        } else {
            while (g_bar_gen == gen) { }
        }
        __threadfence();
    }
    __syncthreads();
}

// ---------------- complex helpers ----------------
__device__ __forceinline__ float2 cmul(float2 a, float2 b) {
    return make_float2(a.x * b.x - a.y * b.y, a.x * b.y + a.y * b.x);
}
__device__ __forceinline__ float2 cadd(float2 a, float2 b) {
    return make_float2(a.x + b.x, a.y + b.y);
}

__constant__ float2 c_P[4][2][2] = {
    { { {1.f,0.f},{0.f,0.f} }, { {0.f,0.f},{1.f,0.f} } },   // I
    { { {0.f,0.f},{1.f,0.f} }, { {1.f,0.f},{0.f,0.f} } },   // X
    { { {0.f,0.f},{0.f,-1.f} }, { {0.f,1.f},{0.f,0.f} } },  // Y
    { { {1.f,0.f},{0.f,0.f} }, { {0.f,0.f},{-1.f,0.f} } },  // Z
};

__constant__ int c_gwa[17] = {0,2,4,6,1,3,5, 1,3,5,7, 0,4,2, 2,6, 0};
__constant__ int c_gwb[17] = {1,3,5,7,2,4,6, 0,2,4,6, 2,6,4, 0,4, 4};

// ---------------- gate-construction helpers ----------------
__device__ __forceinline__ void u3g(float th, float ph, float dl, float2 g[2][2]) {
    float st, ct; __sincosf(0.5f * th, &st, &ct);
    float sp, cp; __sincosf(ph, &sp, &cp);
    float sd, cd; __sincosf(dl, &sd, &cd);
    float spd, cpd; __sincosf(ph + dl, &spd, &cpd);
    g[0][0] = make_float2(ct, 0.f);
    g[0][1] = make_float2(-cd * st, -sd * st);
    g[1][0] = make_float2(cp * st, sp * st);
    g[1][1] = make_float2(cpd * ct, spd * ct);
}

__device__ __forceinline__ void zero4(float2 g[4][4]) {
#pragma unroll
    for (int r = 0; r < 4; r++)
#pragma unroll
        for (int c = 0; c < 4; c++) g[r][c] = make_float2(0.f, 0.f);
}

__device__ __forceinline__ void kron22(const float2 A[2][2], const float2 B[2][2],
                                       float2 P[4][4]) {
#pragma unroll
    for (int ra = 0; ra < 2; ra++)
#pragma unroll
        for (int rb = 0; rb < 2; rb++)
#pragma unroll
            for (int ca = 0; ca < 2; ca++)
#pragma unroll
                for (int cb = 0; cb < 2; cb++)
                    P[ra * 2 + rb][ca * 2 + cb] = cmul(A[ra][ca], B[rb][cb]);
}

__device__ __forceinline__ void mm4(const float2 A[4][4], const float2 B[4][4],
                                    float2 C[4][4]) {
#pragma unroll
    for (int i = 0; i < 4; i++)
#pragma unroll
        for (int j = 0; j < 4; j++) {
            float2 s = make_float2(0.f, 0.f);
#pragma unroll
            for (int k = 0; k < 4; k++) s = cadd(s, cmul(A[i][k], B[k][j]));
            C[i][j] = s;
        }
}

__device__ __forceinline__ float selt(int d, float c, float s) {
    return d == 0 ? 1.f : (d == 1 ? c : s);
}

__device__ __forceinline__ void pdec(int p, int* r, int* c, float* sg) {
    if (p == 2) { r[0] = 0; c[0] = 1; r[1] = 1; c[1] = 0; sg[0] = 1.f; sg[1] = 1.f; }
    else        { r[0] = 0; c[0] = 0; r[1] = 1; c[1] = 1; sg[0] = 1.f; sg[1] = (p == 0 ? 1.f : -1.f); }
}

__device__ void build_gates(const float* __restrict__ conv,
                            const float* __restrict__ pool,
                            const float* __restrict__ last,
                            float2* Gsh, float2 (*Psh)[16], int g) {
    if (g < 16) {
        float2 G[4][4];
        bool is_conv = (g <= 6) || (g >= 11 && g <= 13);
        if (is_conv) {
            int layer, idx;
            if (g <= 6) { const int ii[7] = {0, 2, 4, 6, 1, 3, 5}; layer = 0; idx = ii[g]; }
            else        { const int ii[3] = {0, 2, 1};             layer = 1; idx = ii[g - 11]; }
            const float* cw = conv + layer * 8 * 15;
            float2 A1[2][2], B1[2][2], A2[2][2], B2[2][2];
            u3g(cw[idx * 15 + 0], cw[idx * 15 + 1], cw[idx * 15 + 2], A1);
            u3g(cw[(idx + 1) * 15 + 3], cw[(idx + 1) * 15 + 4], cw[(idx + 1) * 15 + 5], B1);
            u3g(cw[idx * 15 + 9], cw[idx * 15 + 10], cw[idx * 15 + 11], A2);
            u3g(cw[(idx + 1) * 15 + 12], cw[(idx + 1) * 15 + 13], cw[(idx + 1) * 15 + 14], B2);
            float2 P1[4][4], P2[4][4], T1[4][4], T2[4][4], IS[4][4];
            kron22(A1, B1, P1);
            kron22(A2, B2, P2);
            { // ZZ
                float sn, cs; __sincosf(0.5f * cw[idx * 15 + 6], &sn, &cs);
                zero4(IS);
                IS[0][0] = make_float2(cs, -sn);
                IS[1][1] = make_float2(cs, sn);
                IS[2][2] = make_float2(cs, sn);
                IS[3][3] = make_float2(cs, -sn);
                mm4(IS, P1, T1);
            }
            { // YY
                float sn, cs; __sincosf(0.5f * cw[idx * 15 + 7], &sn, &cs);
                zero4(IS);
                IS[0][0] = IS[1][1] = IS[2][2] = IS[3][3] = make_float2(cs, 0.f);
                IS[0][3] = make_float2(0.f, sn);
                IS[1][2] = make_float2(0.f, -sn);
                IS[2][1] = make_float2(0.f, -sn);
                IS[3][0] = make_float2(0.f, sn);
                mm4(IS, T1, T2);
            }
            { // XX
                float sn, cs; __sincosf(0.5f * cw[idx * 15 + 8], &sn, &cs);
                zero4(IS);
                IS[0][0] = IS[1][1] = IS[2][2] = IS[3][3] = make_float2(cs, 0.f);
                IS[0][3] = IS[1][2] = IS[2][1] = IS[3][0] = make_float2(0.f, -sn);
                mm4(IS, T2, T1);
            }
            mm4(P2, T1, G);
        } else {
            int layer = (g <= 10) ? 0 : 1;
            int pi = (g <= 10) ? (g - 7) : (g - 14);
            const float* pw = pool + layer * 4 * 3;
            float2 u[2][2];
            u3g(pw[pi * 3 + 0], pw[pi * 3 + 1], pw[pi * 3 + 2], u);
            zero4(G);
            G[0][0] = make_float2(1.f, 0.f);
            G[1][1] = make_float2(1.f, 0.f);
            G[2][2] = u[0][0]; G[2][3] = u[0][1];
            G[3][2] = u[1][0]; G[3][3] = u[1][1];
        }
#pragma unroll
        for (int r = 0; r < 4; r++)
#pragma unroll
            for (int c = 0; c < 4; c++) Gsh[g * 16 + r * 4 + c] = G[r][c];
    }
    // gate 16: tree product of 15 Pauli rotations (lane 15 = identity)
    {
        float2 Mk[4][4];
        if (g < 15) {
            int pa = (g + 1) >> 2, pb = (g + 1) & 3;
            float sn, cs; __sincosf(0.5f * last[g], &sn, &cs);
#pragma unroll
            for (int r = 0; r < 4; r++)
#pragma unroll
                for (int c = 0; c < 4; c++) {
                    float2 p2 = cmul(c_P[pa][r >> 1][c >> 1], c_P[pb][r & 1][c & 1]);
                    Mk[r][c] = make_float2((r == c ? cs : 0.f) + sn * p2.y, -sn * p2.x);
                }
        } else {
            zero4(Mk);
#pragma unroll
            for (int i = 0; i < 4; i++) Mk[i][i] = make_float2(1.f, 0.f);
        }
        if (g < 16) {
#pragma unroll
            for (int r = 0; r < 4; r++)
#pragma unroll
                for (int c = 0; c < 4; c++) Psh[g][r * 4 + c] = Mk[r][c];
        }
        __syncwarp();
        for (int cnt = 8; cnt >= 1; cnt >>= 1) {
            if (g < cnt) {
                float2 A[4][4], B[4][4], R[4][4];
#pragma unroll
                for (int r = 0; r < 4; r++)
#pragma unroll
                    for (int c = 0; c < 4; c++) {
                        A[r][c] = Psh[2 * g + 1][r * 4 + c];
                        B[r][c] = Psh[2 * g][r * 4 + c];
                    }
                mm4(A, B, R);
                __syncwarp(0xffffffffu >> (32 - cnt));
#pragma unroll
                for (int r = 0; r < 4; r++)
#pragma unroll
                    for (int c = 0; c < 4; c++) Psh[g][r * 4 + c] = R[r][c];
            }
            __syncwarp();
        }
        if (g == 0) {
#pragma unroll
            for (int r = 0; r < 4; r++)
#pragma unroll
                for (int c = 0; c < 4; c++) Gsh[16 * 16 + r * 4 + c] = Psh[0][r * 4 + c];
        }
    }
}

// ================= ONE persistent kernel: everything =================
// smem: FCW half = SM[0..12288), SCRATCH = SM[12288..18656); logits uses all.
__global__ __launch_bounds__(512, 2) void mega_kernel(
    const float* __restrict__ x,
    const float* __restrict__ fcw,
    const float* __restrict__ fcb,
    const float* __restrict__ conv,
    const float* __restrict__ pool,
    const float* __restrict__ last,
    const float* __restrict__ out_w,
    const float* __restrict__ out_b,
    float* __restrict__ out) {
    extern __shared__ __align__(16) float SM[];
    int t = threadIdx.x;
    int b = blockIdx.x;
    float* FCW = SM;

    // ============ S0: load fcw half0 + gates + circuit (col = b) ============
    {
        // fcw half 0 (cols 0..1535)
        for (int idx = t * 4; idx < 12288; idx += 512 * 4) {
            int q = idx / 1536, cc = idx % 1536;
            *(float4*)&FCW[idx] = *(const float4*)&fcw[q * 3072 + cc];
        }
        float2* st = (float2*)(SM + 12288);              // 256 float2
        float2* Gsh = (float2*)(SM + 12800);             // 17*16 float2
        float2 (*Psh)[16] = (float2(*)[16])(SM + 13344); // 16*16 float2
        for (int k = t; k < 256; k += 512)
            st[k] = make_float2(k == b ? 1.f : 0.f, 0.f);
        if (t < 32) build_gates(conv, pool, last, Gsh, Psh, t);
        __syncthreads();

        for (int g = 0; g < 17; g++) {
            float2 g4[4][4];
#pragma unroll
            for (int r = 0; r < 4; r++)
#pragma unroll
                for (int c = 0; c < 4; c++) g4[r][c] = Gsh[g * 16 + r * 4 + c];
            if (t < 64) {
                int wa = c_gwa[g], wb = c_gwb[g];
                int ma = 1 << (7 - wa), mb = 1 << (7 - wb);
                int lo = ma < mb ? ma : mb;
                int hi = ma < mb ? mb : ma;
                int k = t;
                k = ((k & ~(lo - 1)) << 1) | (k & (lo - 1));
                k = ((k & ~(hi - 1)) << 1) | (k & (hi - 1));
                int i0 = k, i1 = k | mb, i2 = k | ma, i3 = k | ma | mb;
                float2 v0 = st[i0], v1 = st[i1], v2 = st[i2], v3 = st[i3];
                float2 o0 = cadd(cadd(cmul(g4[0][0], v0), cmul(g4[0][1], v1)),
                                 cadd(cmul(g4[0][2], v2), cmul(g4[0][3], v3)));
                float2 o1 = cadd(cadd(cmul(g4[1][0], v0), cmul(g4[1][1], v1)),
                                 cadd(cmul(g4[1][2], v2), cmul(g4[1][3], v3)));
                float2 o2 = cadd(cadd(cmul(g4[2][0], v0), cmul(g4[2][1], v1)),
                                 cadd(cmul(g4[2][2], v2), cmul(g4[2][3], v3)));
                float2 o3 = cadd(cadd(cmul(g4[3][0], v0), cmul(g4[3][1], v1)),
                                 cadd(cmul(g4[3][2], v2), cmul(g4[3][3], v3)));
                st[i0] = o0; st[i1] = o1; st[i2] = o2; st[i3] = o3;
            }
            __syncthreads();
        }
        // C transposed: g_Ct[col*256 + kk]; coalesced stores
        if (t < 128) {
            g_Ct[b * 256 + t]       = st[t + 128].x;
            g_Ct[b * 256 + 128 + t] = st[t + 128].y;
        }
    }
    grid_bar();

    // ============ S1: msyrk, all 256 blocks, 16x16 tile each ============
    {
        float* As = SM + 12288;  // [128][16]
        float* Bs = As + 2048;   // [128][16]
        int bi = (b >> 4) * 16, bj = (b & 15) * 16;
        int ty = t >> 4, tx = t & 15;  // used when t<256
        float acc = 0.f;
#pragma unroll
        for (int kc = 0; kc < 256; kc += 128) {
            __syncthreads();
            {
                int ii = t & 15, kb = (t >> 4) * 4;
                float4 va = *(const float4*)&g_Ct[(bi + ii) * 256 + kc + kb];
                float4 vb = *(const float4*)&g_Ct[(bj + ii) * 256 + kc + kb];
                As[(kb + 0) * 16 + ii] = va.x; As[(kb + 1) * 16 + ii] = va.y;
                As[(kb + 2) * 16 + ii] = va.z; As[(kb + 3) * 16 + ii] = va.w;
                Bs[(kb + 0) * 16 + ii] = vb.x; Bs[(kb + 1) * 16 + ii] = vb.y;
                Bs[(kb + 2) * 16 + ii] = vb.z; Bs[(kb + 3) * 16 + ii] = vb.w;
            }
            __syncthreads();
            if (t < 256) {
#pragma unroll 8
                for (int k = 0; k < 128; k++)
                    acc = fmaf(As[k * 16 + ty], Bs[k * 16 + tx], acc);
            }
        }
        if (t < 256) {
            int gi = bi + ty, gj = bj + tx;
            g_M[gi * 256 + gj] = (gi == gj ? 1.f : 0.f) - 2.f * acc;
        }
    }
    grid_bar();

    // ============ S2: pauli (blocks 0..80) then feats (all blocks) ============
    if (b < 81) {
        float* S = SM + 12288;  // <=256 floats used
        int pd[4];
        pd[0] = b / 27; pd[1] = (b / 9) % 3; pd[2] = (b / 3) % 3; pd[3] = b % 3;
        int r[4][2], c[4][2];
        float sg[4][2];
#pragma unroll
        for (int d = 0; d < 4; d++) pdec(pd[d], r[d], c[d], sg[d]);
        if (t < 256) {
            int i = t >> 4, j = t & 15;
            float v = 0.f;
#pragma unroll
            for (int m = 0; m < 16; m++) {
                int t0 = m & 1, t1 = (m >> 1) & 1, t2 = (m >> 2) & 1, t3 = (m >> 3) & 1;
                float s = sg[0][t0] * sg[1][t1] * sg[2][t2] * sg[3][t3];
                int ri = i + 128 * r[0][t0] + 64 * r[1][t1] + 32 * r[2][t2] + 16 * r[3][t3];
                int cj = j + 128 * c[0][t0] + 64 * c[1][t1] + 32 * c[2][t2] + 16 * c[3][t3];
                v += s * g_M[ri * 256 + cj];
            }
            S[t] = v;
        }
        __syncthreads();
        int nc = 1;
        for (int d = 4; d < 8; d++) {
            int sh = 7 - d;
            int half = 1 << sh;
            int hh = half * half;
            int n_out = nc * 3 * hh;
            int in_blk = 4 * hh;
            int full = half << 1;
            float v = 0.f;
            bool act = (t < n_out);
            if (act) {
                int j = t & (half - 1);
                int rr = t >> sh;
                int i = rr & (half - 1);
                int r2 = rr >> sh;
                int p = r2 % 3;
                int cc = r2 / 3;
                const float* base = S + cc * in_blk;
                if (p == 0)      v = base[i * full + j] + base[(i + half) * full + j + half];
                else if (p == 1) v = base[i * full + j] - base[(i + half) * full + j + half];
                else             v = base[i * full + j + half] + base[(i + half) * full + j];
            }
            __syncthreads();
            if (act) S[t] = v;
            __syncthreads();
            nc *= 3;
        }
        for (int o = t; o < 81; o += 512) g_T[b * 81 + o] = S[o];
    }
    // feats: 32 rows per block (2 rows/warp), two fcw column-halves
    {
        int warp = t >> 5, lane = t & 31;
        int row0 = b * 32 + warp * 2;
        float acc[8][2];
#pragma unroll
        for (int q = 0; q < 8; q++) { acc[q][0] = 0.f; acc[q][1] = 0.f; }

#pragma unroll
        for (int h = 0; h < 2; h++) {
            if (h == 1) {
                __syncthreads();
                for (int idx = t * 4; idx < 12288; idx += 512 * 4) {
                    int q = idx / 1536, cc = idx % 1536;
                    *(float4*)&FCW[idx] = *(const float4*)&fcw[q * 3072 + 1536 + cc];
                }
                __syncthreads();
            }
            int gbase = h * 1536;
#pragma unroll 4
            for (int it = 0; it < 12; it++) {
                int cl = (it * 32 + lane) * 4;
                float4 xv0 = *(const float4*)&x[(long long)row0 * 3072 + gbase + cl];
                float4 xv1 = *(const float4*)&x[(long long)(row0 + 1) * 3072 + gbase + cl];
#pragma unroll
                for (int q = 0; q < 8; q++) {
                    float4 wv = *(const float4*)&FCW[q * 1536 + cl];
                    acc[q][0] += wv.x * xv0.x + wv.y * xv0.y + wv.z * xv0.z + wv.w * xv0.w;
                    acc[q][1] += wv.x * xv1.x + wv.y * xv1.y + wv.z * xv1.z + wv.w * xv1.w;
                }
            }
        }
#pragma unroll
        for (int q = 0; q < 8; q++) {
#pragma unroll
            for (int rr = 0; rr < 2; rr++) {
                float v = acc[q][rr];
                v += __shfl_down_sync(0xffffffffu, v, 16);
                v += __shfl_down_sync(0xffffffffu, v, 8);
                v += __shfl_down_sync(0xffffffffu, v, 4);
                v += __shfl_down_sync(0xffffffffu, v, 2);
                v += __shfl_down_sync(0xffffffffu, v, 1);
                if (lane == 0) g_feats[(row0 + rr) * 8 + q] = tanhf(v + fcb[q]);
            }
        }
    }
    grid_bar();

    // ============ S3: logits (blocks 0..127, 64 samples each) ============
    if (b < 128) {
        float* Tsh = SM;                 // 81*84 = 6804
        float* ash = Tsh + 81 * 84;      // 64*84 = 5376
        float* bsh = ash + 64 * 84;      // 64*84
        float* qps = bsh + 64 * 84;      // 64*16
        float* qvs = qps + 64 * 16;      // 64

        for (int i = t; i < 81 * 84; i += 512) Tsh[i] = 0.f;
        for (int i = t; i < 64 * 84; i += 512) bsh[i] = 0.f;
        __syncthreads();
        for (int i = t; i < 6561; i += 512) Tsh[(i / 81) * 84 + (i % 81)] = g_T[i];

        if (t < 256) {
            int s = t >> 2, part = t & 3;
            int sgi = b * 64 + s;
            float tc8[8], ts8[8];
#pragma unroll
            for (int w = 0; w < 8; w++) {
                float f = g_feats[sgi * 8 + w];
                __sincosf(f, &ts8[w], &tc8[w]);
            }
            int m0 = part * 21;
            int m1 = m0 + 21; if (m1 > 81) m1 = 81;
            for (int m = m0; m < m1; m++) {
                int d0 = m / 27, d1 = (m / 9) % 3, d2 = (m / 3) % 3, d3 = m % 3;
                ash[s * 84 + m] = selt(d0, tc8[0], ts8[0]) * selt(d1, tc8[1], ts8[1]) *
                                  selt(d2, tc8[2], ts8[2]) * selt(d3, tc8[3], ts8[3]);
                bsh[s * 84 + m] = selt(d0, tc8[4], ts8[4]) * selt(d1, tc8[5], ts8[5]) *
                                  selt(d2, tc8[6], ts8[6]) * selt(d3, tc8[7], ts8[7]);
            }
        }
        __syncthreads();

        if (t < 224) {
            int sg2 = t / 14, ng = t % 14;
            int s0 = sg2 * 4, n0 = ng * 6;
            float e[4][6];
#pragma unroll
            for (int i = 0; i < 4; i++)
#pragma unroll
                for (int j = 0; j < 6; j++) e[i][j] = 0.f;
            for (int m = 0; m < 81; m++) {
                float tv[6];
#pragma unroll
                for (int j = 0; j < 6; j++) tv[j] = Tsh[m * 84 + n0 + j];
#pragma unroll
                for (int i = 0; i < 4; i++) {
                    float av = ash[(s0 + i) * 84 + m];
#pragma unroll
                    for (int j = 0; j < 6; j++) e[i][j] = fmaf(av, tv[j], e[i][j]);
                }
            }
#pragma unroll
            for (int i = 0; i < 4; i++) {
                float q = 0.f;
#pragma unroll
                for (int j = 0; j < 6; j++) q += e[i][j] * bsh[(s0 + i) * 84 + n0 + j];
                qps[(s0 + i) * 16 + ng] = q;
            }
        }
        __syncthreads();
        if (t < 64) {
            float q = 0.f;
#pragma unroll
            for (int k = 0; k < 14; k++) q += qps[t * 16 + k];
            qvs[t] = q * (1.0f / 256.0f);
        }
        __syncthreads();
        for (int i = t; i < 640; i += 512) {
            int s = i / 10, c = i % 10;
            out[(b * 64 + s) * 10 + c] = qvs[s] * out_w[c] + out_b[c];
        }
    }
}

// ---------------- launch: ONE kernel ----------------
extern "C" void kernel_launch(void* const* d_in, const int* in_sizes, int n_in,
                              void* d_out, int out_size) {
    const float* x     = (const float*)d_in[0];
    const float* fcw   = (const float*)d_in[1];
    const float* fcb   = (const float*)d_in[2];
    const float* conv  = (const float*)d_in[3];
    const float* pool  = (const float*)d_in[4];
    const float* last  = (const float*)d_in[5];
    const float* out_w = (const float*)d_in[6];
    const float* out_b = (const float*)d_in[7];
    float* out = (float*)d_out;

    static bool inited = false;
    if (!inited) {
        cudaFuncSetAttribute(mega_kernel, cudaFuncAttributeMaxDynamicSharedMemorySize, SMEM_BYTES);
        inited = true;
    }

    mega_kernel<<<NBLK, 512, SMEM_BYTES>>>(x, fcw, fcb, conv, pool, last, out_w, out_b, out);
}